// round 1
// baseline (speedup 1.0000x reference)
#include <cuda_runtime.h>
#include <math.h>

#define BB 2
#define SS 4096
#define EE 1024
#define HH 16
#define DD 64
#define WIN_ 256
#define MM (BB*SS)   // 8192

// scratch (allocation-free: __device__ globals)
static __device__ float g_q[(size_t)BB*HH*SS*DD];   // [b][h][s][d], rope'd + scaled
static __device__ float g_k[(size_t)BB*HH*SS*DD];   // [b][h][s][d], rope'd
static __device__ float g_v[(size_t)BB*HH*SS*DD];   // [b][h][s][d]
static __device__ float g_ctx[(size_t)MM*EE];       // [b][s][e]

// rope over the HEAD axis: angle = head_idx * 10000^{-(j%32)/32}, interleaved rotation
__device__ __forceinline__ void rope_pair(float& v0, float& v1, int h, int j) {
    const float C = 0.28782313662425572f; // ln(10000)/32
    float invA = __expf(-(float)( j      & 31) * C);
    float invB = __expf(-(float)((j + 1) & 31) * C);
    float sa, ca, sb, cb;
    __sincosf((float)h * invA, &sa, &ca);
    __sincosf((float)h * invB, &sb, &cb);
    float r0 = v0 * ca - v1 * sa;
    float r1 = v1 * cb + v0 * sb;
    v0 = r0; v1 = r1;
}

// ---------------- projection GEMM: out = X @ W^T + b ----------------
// MODE 0: X = x, z in {0,1,2} selects (Wq,Wk,Wv); rope epilogue; writes g_q/g_k/g_v [b,h,s,d]
// MODE 1: X = g_ctx, W0 = Wo; writes d_out [m,n] row-major
template<int MODE>
__global__ __launch_bounds__(256)
void proj_kernel(const float* __restrict__ X,
                 const float* __restrict__ W0, const float* __restrict__ W1,
                 const float* __restrict__ W2,
                 const float* __restrict__ b0, const float* __restrict__ b1,
                 const float* __restrict__ b2,
                 float* __restrict__ out)
{
    __shared__ float As[16][132];
    __shared__ float Bs[16][132];

    const int z = blockIdx.z;
    const float* A    = (MODE == 1) ? (const float*)g_ctx : X;
    const float* W    = (MODE == 1) ? W0 : (z == 0 ? W0 : (z == 1 ? W1 : W2));
    const float* bias = (MODE == 1) ? b0 : (z == 0 ? b0 : (z == 1 ? b1 : b2));

    const int tid = threadIdx.x;
    const int tx = tid & 15, ty = tid >> 4;
    const int mBase = blockIdx.y * 128;
    const int nBase = blockIdx.x * 128;

    float acc[8][8];
    #pragma unroll
    for (int i = 0; i < 8; i++)
        #pragma unroll
        for (int j = 0; j < 8; j++) acc[i][j] = 0.f;

    for (int k0 = 0; k0 < EE; k0 += 16) {
        #pragma unroll
        for (int p = 0; p < 2; p++) {
            int o = tid * 4 + p * 1024;
            int r = o >> 4, cc = o & 15;
            float4 av = *reinterpret_cast<const float4*>(&A[(size_t)(mBase + r) * EE + k0 + cc]);
            As[cc + 0][r] = av.x; As[cc + 1][r] = av.y;
            As[cc + 2][r] = av.z; As[cc + 3][r] = av.w;
            float4 bv = *reinterpret_cast<const float4*>(&W[(size_t)(nBase + r) * EE + k0 + cc]);
            Bs[cc + 0][r] = bv.x; Bs[cc + 1][r] = bv.y;
            Bs[cc + 2][r] = bv.z; Bs[cc + 3][r] = bv.w;
        }
        __syncthreads();
        #pragma unroll
        for (int kk = 0; kk < 16; kk++) {
            float a[8], b[8];
            #pragma unroll
            for (int i = 0; i < 4; i++) {
                a[i]     = As[kk][ty * 4 + i];
                a[4 + i] = As[kk][64 + ty * 4 + i];
            }
            #pragma unroll
            for (int j = 0; j < 4; j++) {
                b[j]     = Bs[kk][tx * 4 + j];
                b[4 + j] = Bs[kk][64 + tx * 4 + j];
            }
            #pragma unroll
            for (int i = 0; i < 8; i++)
                #pragma unroll
                for (int j = 0; j < 8; j++)
                    acc[i][j] = fmaf(a[i], b[j], acc[i][j]);
        }
        __syncthreads();
    }

    // epilogue
    #pragma unroll
    for (int ig = 0; ig < 2; ig++) {
        #pragma unroll
        for (int i = 0; i < 4; i++) {
            int m = mBase + ig * 64 + ty * 4 + i;
            int bb = m >> 12;        // / 4096
            int srow = m & 4095;
            #pragma unroll
            for (int jg = 0; jg < 2; jg++) {
                int colb = jg * 64 + tx * 4;
                int n = nBase + colb;
                float v0 = acc[ig * 4 + i][jg * 4 + 0] + bias[n + 0];
                float v1 = acc[ig * 4 + i][jg * 4 + 1] + bias[n + 1];
                float v2 = acc[ig * 4 + i][jg * 4 + 2] + bias[n + 2];
                float v3 = acc[ig * 4 + i][jg * 4 + 3] + bias[n + 3];
                if (MODE == 1) {
                    float4 o4 = make_float4(v0, v1, v2, v3);
                    *reinterpret_cast<float4*>(&out[(size_t)m * EE + n]) = o4;
                } else {
                    int h = n >> 6;
                    int j = n & 63;              // multiple of 4 -> pairs (j,j+1),(j+2,j+3)
                    if (z <= 1) {
                        rope_pair(v0, v1, h, j);
                        rope_pair(v2, v3, h, j + 2);
                    }
                    if (z == 0) { v0 *= 0.125f; v1 *= 0.125f; v2 *= 0.125f; v3 *= 0.125f; }
                    float* dst = (z == 0) ? g_q : (z == 1) ? g_k : g_v;
                    size_t idx = (((size_t)bb * HH + h) * SS + srow) * DD + j;
                    float4 o4 = make_float4(v0, v1, v2, v3);
                    *reinterpret_cast<float4*>(&dst[idx]) = o4;
                }
            }
        }
    }
}

// ---------------- sliding-window attention (flash-style) ----------------
// grid (qb=4, c=16, bh=32); block 256; 64 queries x 64-key tiles, frag 4x4
#define SM_STRIDE 65
#define SMEM_ATTN (4 * 64 * SM_STRIDE * (int)sizeof(float))

__global__ __launch_bounds__(256)
void attn_kernel()
{
    extern __shared__ float smx[];
    float* Qs = smx;
    float* Ks = smx + 1 * 64 * SM_STRIDE;
    float* Vs = smx + 2 * 64 * SM_STRIDE;
    float* Ps = smx + 3 * 64 * SM_STRIDE;

    const int qb = blockIdx.x;
    const int c  = blockIdx.y;
    const int bh = blockIdx.z;
    const int tid = threadIdx.x;
    const int tx = tid & 15, ty = tid >> 4;

    const float* Qg = g_q + (size_t)bh * SS * DD;
    const float* Kg = g_k + (size_t)bh * SS * DD;
    const float* Vg = g_v + (size_t)bh * SS * DD;

    const int q0 = c * WIN_ + qb * 64;

    #pragma unroll
    for (int p = 0; p < 4; p++) {
        int o = tid * 4 + p * 1024;
        int r = o >> 6, dc = o & 63;
        float4 v = *reinterpret_cast<const float4*>(&Qg[(size_t)(q0 + r) * DD + dc]);
        Qs[r * SM_STRIDE + dc + 0] = v.x;
        Qs[r * SM_STRIDE + dc + 1] = v.y;
        Qs[r * SM_STRIDE + dc + 2] = v.z;
        Qs[r * SM_STRIDE + dc + 3] = v.w;
    }

    float accO[4][4];
    float mrow[4], lrow[4];
    #pragma unroll
    for (int i = 0; i < 4; i++) {
        mrow[i] = -1e30f; lrow[i] = 0.f;
        #pragma unroll
        for (int j = 0; j < 4; j++) accO[i][j] = 0.f;
    }

    // key tiles intersecting this 64-query block's window: kt in [qb, qb+8]
    for (int kt = qb; kt <= qb + 8; kt++) {
        const int kbase = c * WIN_ - WIN_ + kt * 64;
        if (kbase >= SS || kbase + 63 < 0) continue;   // tiles are 64-aligned: fully in or fully out

        #pragma unroll
        for (int p = 0; p < 4; p++) {
            int o = tid * 4 + p * 1024;
            int r = o >> 6, dc = o & 63;
            int kp = kbase + r;
            float4 kv = *reinterpret_cast<const float4*>(&Kg[(size_t)kp * DD + dc]);
            float4 vv = *reinterpret_cast<const float4*>(&Vg[(size_t)kp * DD + dc]);
            Ks[r * SM_STRIDE + dc + 0] = kv.x; Ks[r * SM_STRIDE + dc + 1] = kv.y;
            Ks[r * SM_STRIDE + dc + 2] = kv.z; Ks[r * SM_STRIDE + dc + 3] = kv.w;
            Vs[r * SM_STRIDE + dc + 0] = vv.x; Vs[r * SM_STRIDE + dc + 1] = vv.y;
            Vs[r * SM_STRIDE + dc + 2] = vv.z; Vs[r * SM_STRIDE + dc + 3] = vv.w;
        }
        __syncthreads();

        // S = Q K^T (64x64 tile, 4x4 frag)
        float s[4][4];
        #pragma unroll
        for (int i = 0; i < 4; i++)
            #pragma unroll
            for (int j = 0; j < 4; j++) s[i][j] = 0.f;

        #pragma unroll 8
        for (int dd = 0; dd < 64; dd++) {
            float a[4], b[4];
            #pragma unroll
            for (int i = 0; i < 4; i++) a[i] = Qs[(ty * 4 + i) * SM_STRIDE + dd];
            #pragma unroll
            for (int j = 0; j < 4; j++) b[j] = Ks[(tx * 4 + j) * SM_STRIDE + dd];
            #pragma unroll
            for (int i = 0; i < 4; i++)
                #pragma unroll
                for (int j = 0; j < 4; j++)
                    s[i][j] = fmaf(a[i], b[j], s[i][j]);
        }

        // mask + online softmax (row = 16 threads in one half-warp)
        #pragma unroll
        for (int i = 0; i < 4; i++) {
            int qp = q0 + ty * 4 + i;
            float mx = -1e30f;
            #pragma unroll
            for (int j = 0; j < 4; j++) {
                int kp = kbase + tx * 4 + j;
                bool ok = (kp >= qp - WIN_) && (kp <= qp + WIN_);
                s[i][j] = ok ? s[i][j] : -1e30f;
                mx = fmaxf(mx, s[i][j]);
            }
            mx = fmaxf(mx, __shfl_xor_sync(0xffffffffu, mx, 1));
            mx = fmaxf(mx, __shfl_xor_sync(0xffffffffu, mx, 2));
            mx = fmaxf(mx, __shfl_xor_sync(0xffffffffu, mx, 4));
            mx = fmaxf(mx, __shfl_xor_sync(0xffffffffu, mx, 8));
            float mnew = fmaxf(mrow[i], mx);
            float fac = __expf(mrow[i] - mnew);
            float pv[4];
            float rs = 0.f;
            #pragma unroll
            for (int j = 0; j < 4; j++) {
                pv[j] = (s[i][j] < -1e29f) ? 0.f : __expf(s[i][j] - mnew);
                rs += pv[j];
            }
            rs += __shfl_xor_sync(0xffffffffu, rs, 1);
            rs += __shfl_xor_sync(0xffffffffu, rs, 2);
            rs += __shfl_xor_sync(0xffffffffu, rs, 4);
            rs += __shfl_xor_sync(0xffffffffu, rs, 8);
            mrow[i] = mnew;
            lrow[i] = lrow[i] * fac + rs;
            #pragma unroll
            for (int j = 0; j < 4; j++) accO[i][j] *= fac;
            #pragma unroll
            for (int j = 0; j < 4; j++)
                Ps[(ty * 4 + i) * SM_STRIDE + tx * 4 + j] = pv[j];
        }
        __syncthreads();

        // O += P @ V
        #pragma unroll 8
        for (int kk = 0; kk < 64; kk++) {
            float a[4], b[4];
            #pragma unroll
            for (int i = 0; i < 4; i++) a[i] = Ps[(ty * 4 + i) * SM_STRIDE + kk];
            #pragma unroll
            for (int j = 0; j < 4; j++) b[j] = Vs[kk * SM_STRIDE + tx * 4 + j];
            #pragma unroll
            for (int i = 0; i < 4; i++)
                #pragma unroll
                for (int j = 0; j < 4; j++)
                    accO[i][j] = fmaf(a[i], b[j], accO[i][j]);
        }
        __syncthreads();
    }

    // write ctx [b][s][e]
    const int b = bh >> 4, h = bh & 15;
    #pragma unroll
    for (int i = 0; i < 4; i++) {
        int sp = q0 + ty * 4 + i;
        float inv = 1.f / lrow[i];
        float4 o4 = make_float4(accO[i][0] * inv, accO[i][1] * inv,
                                accO[i][2] * inv, accO[i][3] * inv);
        *reinterpret_cast<float4*>(
            &g_ctx[((size_t)(b * SS + sp)) * EE + h * DD + tx * 4]) = o4;
    }
}

extern "C" void kernel_launch(void* const* d_in, const int* in_sizes, int n_in,
                              void* d_out, int out_size)
{
    (void)in_sizes; (void)n_in; (void)out_size;
    const float* x  = (const float*)d_in[0];
    const float* Wq = (const float*)d_in[1];
    const float* bq = (const float*)d_in[2];
    const float* Wk = (const float*)d_in[3];
    const float* bk = (const float*)d_in[4];
    const float* Wv = (const float*)d_in[5];
    const float* bv = (const float*)d_in[6];
    const float* Wo = (const float*)d_in[7];
    const float* bo = (const float*)d_in[8];
    float* out = (float*)d_out;

    cudaFuncSetAttribute(attn_kernel, cudaFuncAttributeMaxDynamicSharedMemorySize, SMEM_ATTN);

    dim3 gq(EE / 128, MM / 128, 3);
    proj_kernel<0><<<gq, 256>>>(x, Wq, Wk, Wv, bq, bk, bv, nullptr);

    attn_kernel<<<dim3(4, 16, BB * HH), 256, SMEM_ATTN>>>();

    dim3 go(EE / 128, MM / 128, 1);
    proj_kernel<1><<<go, 256>>>(nullptr, Wo, nullptr, nullptr, bo, nullptr, nullptr, out);
}

// round 4
// speedup vs baseline: 2.9249x; 2.9249x over previous
#include <cuda_runtime.h>
#include <math.h>
#include <stdint.h>

#define BB 2
#define SS 4096
#define EE 1024
#define HH 16
#define DD 64
#define WIN_ 256
#define MM (BB*SS)   // 8192

// scratch (allocation-free: __device__ globals)
static __device__ float g_q[(size_t)BB*HH*SS*DD];   // [b][h][s][d], rope'd + scaled
static __device__ float g_k[(size_t)BB*HH*SS*DD];   // [b][h][s][d], rope'd
static __device__ float g_v[(size_t)BB*HH*SS*DD];   // [b][h][s][d]
static __device__ float g_ctx[(size_t)MM*EE];       // [b][s][e]

// rope over the HEAD axis: angle = head_idx * 10000^{-(j%32)/32}, interleaved rotation
__device__ __forceinline__ void rope_pair(float& v0, float& v1, int h, int j) {
    const float C = 0.28782313662425572f; // ln(10000)/32
    float invA = __expf(-(float)( j      & 31) * C);
    float invB = __expf(-(float)((j + 1) & 31) * C);
    float sa, ca, sb, cb;
    __sincosf((float)h * invA, &sa, &ca);
    __sincosf((float)h * invB, &sb, &cb);
    float r0 = v0 * ca - v1 * sa;
    float r1 = v1 * cb + v0 * sb;
    v0 = r0; v1 = r1;
}

__device__ __forceinline__ uint32_t f2tf(float f) {
    uint32_t u;
    asm("cvt.rna.tf32.f32 %0, %1;" : "=r"(u) : "f"(f));
    return u;
}

__device__ __forceinline__ void mma_tf32(float (&c)[4], const uint32_t (&a)[4], const uint32_t (&b)[2]) {
    asm volatile(
        "mma.sync.aligned.m16n8k8.row.col.f32.tf32.tf32.f32 "
        "{%0,%1,%2,%3},{%4,%5,%6,%7},{%8,%9},{%0,%1,%2,%3};"
        : "+f"(c[0]), "+f"(c[1]), "+f"(c[2]), "+f"(c[3])
        : "r"(a[0]), "r"(a[1]), "r"(a[2]), "r"(a[3]), "r"(b[0]), "r"(b[1]));
}

// ---------------- projection GEMM (TF32 tensor cores): out = X @ W^T + b ----------------
// MODE 0: X = x, z selects (Wq,Wk,Wv); rope epilogue; writes g_q/g_k/g_v [b,h,s,d]
// MODE 1: X = g_ctx, W0 = Wo; writes d_out [m,n]
#define ASTRIDE 36                              // floats; stride 36 -> frag LDS conflict-free
#define SMEM_PROJ (4 * 128 * ASTRIDE * 4)       // 2 stages x (A + B) tiles = 73728 B

template<int MODE>
__global__ __launch_bounds__(256)
void proj_mma(const float* __restrict__ X,
              const float* __restrict__ W0, const float* __restrict__ W1,
              const float* __restrict__ W2,
              const float* __restrict__ b0, const float* __restrict__ b1,
              const float* __restrict__ b2,
              float* __restrict__ out)
{
    extern __shared__ uint32_t sm_u[];
    uint32_t* As = sm_u;                       // [2][128][ASTRIDE]
    uint32_t* Bs = sm_u + 2 * 128 * ASTRIDE;   // [2][128][ASTRIDE]

    const int z = blockIdx.z;
    const float* A    = (MODE == 1) ? (const float*)g_ctx : X;
    const float* W    = (MODE == 1) ? W0 : (z == 0 ? W0 : (z == 1 ? W1 : W2));
    const float* bias = (MODE == 1) ? b0 : (z == 0 ? b0 : (z == 1 ? b1 : b2));

    const int tid   = threadIdx.x;
    const int lane  = tid & 31;
    const int warp  = tid >> 5;
    const int warpM = warp >> 2;               // 0..1 -> 64-row slab
    const int warpN = warp & 3;                // 0..3 -> 32-col slab
    const int grp   = lane >> 2;               // 0..7
    const int qid   = lane & 3;                // 0..3
    const int mBase = blockIdx.y * 128;
    const int nBase = blockIdx.x * 128;

    const int ldRow = tid >> 3;                // 0..31
    const int ldCol = (tid & 7) * 4;           // 0..28

    float4 ra[4], rb[4];

    // prologue: load k-slab 0
    #pragma unroll
    for (int p = 0; p < 4; p++) {
        ra[p] = *reinterpret_cast<const float4*>(&A[(size_t)(mBase + ldRow + p * 32) * EE + ldCol]);
        rb[p] = *reinterpret_cast<const float4*>(&W[(size_t)(nBase + ldRow + p * 32) * EE + ldCol]);
    }
    #pragma unroll
    for (int p = 0; p < 4; p++) {
        int r = ldRow + p * 32;
        uint4 ua = make_uint4(f2tf(ra[p].x), f2tf(ra[p].y), f2tf(ra[p].z), f2tf(ra[p].w));
        uint4 ub = make_uint4(f2tf(rb[p].x), f2tf(rb[p].y), f2tf(rb[p].z), f2tf(rb[p].w));
        *reinterpret_cast<uint4*>(&As[r * ASTRIDE + ldCol]) = ua;
        *reinterpret_cast<uint4*>(&Bs[r * ASTRIDE + ldCol]) = ub;
    }
    __syncthreads();

    float acc[4][4][4];
    #pragma unroll
    for (int mf = 0; mf < 4; mf++)
        #pragma unroll
        for (int nf = 0; nf < 4; nf++)
            #pragma unroll
            for (int r = 0; r < 4; r++) acc[mf][nf][r] = 0.f;

    const int NIT = EE / 32;   // 32
    for (int k0 = 0; k0 < NIT; k0++) {
        const int cur = k0 & 1;
        const bool more = (k0 + 1 < NIT);
        if (more) {
            int kofs = (k0 + 1) * 32 + ldCol;
            #pragma unroll
            for (int p = 0; p < 4; p++) {
                ra[p] = *reinterpret_cast<const float4*>(&A[(size_t)(mBase + ldRow + p * 32) * EE + kofs]);
                rb[p] = *reinterpret_cast<const float4*>(&W[(size_t)(nBase + ldRow + p * 32) * EE + kofs]);
            }
        }

        const uint32_t* Ac = As + cur * 128 * ASTRIDE;
        const uint32_t* Bc = Bs + cur * 128 * ASTRIDE;

        #pragma unroll
        for (int ks = 0; ks < 4; ks++) {
            uint32_t af[4][4];
            #pragma unroll
            for (int mf = 0; mf < 4; mf++) {
                int base = (warpM * 64 + mf * 16 + grp) * ASTRIDE + ks * 8 + qid;
                af[mf][0] = Ac[base];
                af[mf][1] = Ac[base + 8 * ASTRIDE];
                af[mf][2] = Ac[base + 4];
                af[mf][3] = Ac[base + 8 * ASTRIDE + 4];
            }
            uint32_t bf[4][2];
            #pragma unroll
            for (int nf = 0; nf < 4; nf++) {
                int base = (warpN * 32 + nf * 8 + grp) * ASTRIDE + ks * 8 + qid;
                bf[nf][0] = Bc[base];
                bf[nf][1] = Bc[base + 4];
            }
            #pragma unroll
            for (int mf = 0; mf < 4; mf++)
                #pragma unroll
                for (int nf = 0; nf < 4; nf++)
                    mma_tf32(acc[mf][nf], af[mf], bf[nf]);
        }

        if (more) {
            const int nxt = (k0 + 1) & 1;
            uint32_t* An = As + nxt * 128 * ASTRIDE;
            uint32_t* Bn = Bs + nxt * 128 * ASTRIDE;
            #pragma unroll
            for (int p = 0; p < 4; p++) {
                int r = ldRow + p * 32;
                uint4 ua = make_uint4(f2tf(ra[p].x), f2tf(ra[p].y), f2tf(ra[p].z), f2tf(ra[p].w));
                uint4 ub = make_uint4(f2tf(rb[p].x), f2tf(rb[p].y), f2tf(rb[p].z), f2tf(rb[p].w));
                *reinterpret_cast<uint4*>(&An[r * ASTRIDE + ldCol]) = ua;
                *reinterpret_cast<uint4*>(&Bn[r * ASTRIDE + ldCol]) = ub;
            }
        }
        __syncthreads();
    }

    // epilogue: bias (+rope/scale for MODE 0), scatter
    #pragma unroll
    for (int mf = 0; mf < 4; mf++) {
        #pragma unroll
        for (int half = 0; half < 2; half++) {
            int row = mBase + warpM * 64 + mf * 16 + grp + half * 8;
            int bb   = row >> 12;
            int srow = row & 4095;
            #pragma unroll
            for (int nf = 0; nf < 4; nf++) {
                int col = nBase + warpN * 32 + nf * 8 + qid * 2;
                float v0 = acc[mf][nf][half * 2 + 0] + bias[col];
                float v1 = acc[mf][nf][half * 2 + 1] + bias[col + 1];
                if (MODE == 1) {
                    *reinterpret_cast<float2*>(&out[(size_t)row * EE + col]) = make_float2(v0, v1);
                } else {
                    int h = col >> 6;
                    int j = col & 63;     // even
                    if (z <= 1) rope_pair(v0, v1, h, j);
                    if (z == 0) { v0 *= 0.125f; v1 *= 0.125f; }
                    float* dst = (z == 0) ? g_q : (z == 1) ? g_k : g_v;
                    size_t idx = (((size_t)bb * HH + h) * SS + srow) * DD + j;
                    *reinterpret_cast<float2*>(&dst[idx]) = make_float2(v0, v1);
                }
            }
        }
    }
}

// ---------------- sliding-window attention (flash-style, fp32 SIMT) ----------------
#define SM_STRIDE 65
#define SMEM_ATTN (4 * 64 * SM_STRIDE * (int)sizeof(float))

__global__ __launch_bounds__(256)
void attn_kernel()
{
    extern __shared__ float smx[];
    float* Qs = smx;
    float* Ks = smx + 1 * 64 * SM_STRIDE;
    float* Vs = smx + 2 * 64 * SM_STRIDE;
    float* Ps = smx + 3 * 64 * SM_STRIDE;

    const int qb = blockIdx.x;
    const int c  = blockIdx.y;
    const int bh = blockIdx.z;
    const int tid = threadIdx.x;
    const int tx = tid & 15, ty = tid >> 4;

    const float* Qg = g_q + (size_t)bh * SS * DD;
    const float* Kg = g_k + (size_t)bh * SS * DD;
    const float* Vg = g_v + (size_t)bh * SS * DD;

    const int q0 = c * WIN_ + qb * 64;

    #pragma unroll
    for (int p = 0; p < 4; p++) {
        int o = tid * 4 + p * 1024;
        int r = o >> 6, dc = o & 63;
        float4 v = *reinterpret_cast<const float4*>(&Qg[(size_t)(q0 + r) * DD + dc]);
        Qs[r * SM_STRIDE + dc + 0] = v.x;
        Qs[r * SM_STRIDE + dc + 1] = v.y;
        Qs[r * SM_STRIDE + dc + 2] = v.z;
        Qs[r * SM_STRIDE + dc + 3] = v.w;
    }

    float accO[4][4];
    float mrow[4], lrow[4];
    #pragma unroll
    for (int i = 0; i < 4; i++) {
        mrow[i] = -1e30f; lrow[i] = 0.f;
        #pragma unroll
        for (int j = 0; j < 4; j++) accO[i][j] = 0.f;
    }

    for (int kt = qb; kt <= qb + 8; kt++) {
        const int kbase = c * WIN_ - WIN_ + kt * 64;
        if (kbase >= SS || kbase + 63 < 0) continue;

        #pragma unroll
        for (int p = 0; p < 4; p++) {
            int o = tid * 4 + p * 1024;
            int r = o >> 6, dc = o & 63;
            int kp = kbase + r;
            float4 kv = *reinterpret_cast<const float4*>(&Kg[(size_t)kp * DD + dc]);
            float4 vv = *reinterpret_cast<const float4*>(&Vg[(size_t)kp * DD + dc]);
            Ks[r * SM_STRIDE + dc + 0] = kv.x; Ks[r * SM_STRIDE + dc + 1] = kv.y;
            Ks[r * SM_STRIDE + dc + 2] = kv.z; Ks[r * SM_STRIDE + dc + 3] = kv.w;
            Vs[r * SM_STRIDE + dc + 0] = vv.x; Vs[r * SM_STRIDE + dc + 1] = vv.y;
            Vs[r * SM_STRIDE + dc + 2] = vv.z; Vs[r * SM_STRIDE + dc + 3] = vv.w;
        }
        __syncthreads();

        float s[4][4];
        #pragma unroll
        for (int i = 0; i < 4; i++)
            #pragma unroll
            for (int j = 0; j < 4; j++) s[i][j] = 0.f;

        #pragma unroll 8
        for (int dd = 0; dd < 64; dd++) {
            float a[4], b[4];
            #pragma unroll
            for (int i = 0; i < 4; i++) a[i] = Qs[(ty * 4 + i) * SM_STRIDE + dd];
            #pragma unroll
            for (int j = 0; j < 4; j++) b[j] = Ks[(tx * 4 + j) * SM_STRIDE + dd];
            #pragma unroll
            for (int i = 0; i < 4; i++)
                #pragma unroll
                for (int j = 0; j < 4; j++)
                    s[i][j] = fmaf(a[i], b[j], s[i][j]);
        }

        #pragma unroll
        for (int i = 0; i < 4; i++) {
            int qp = q0 + ty * 4 + i;
            float mx = -1e30f;
            #pragma unroll
            for (int j = 0; j < 4; j++) {
                int kp = kbase + tx * 4 + j;
                bool ok = (kp >= qp - WIN_) && (kp <= qp + WIN_);
                s[i][j] = ok ? s[i][j] : -1e30f;
                mx = fmaxf(mx, s[i][j]);
            }
            mx = fmaxf(mx, __shfl_xor_sync(0xffffffffu, mx, 1));
            mx = fmaxf(mx, __shfl_xor_sync(0xffffffffu, mx, 2));
            mx = fmaxf(mx, __shfl_xor_sync(0xffffffffu, mx, 4));
            mx = fmaxf(mx, __shfl_xor_sync(0xffffffffu, mx, 8));
            float mnew = fmaxf(mrow[i], mx);
            float fac = __expf(mrow[i] - mnew);
            float pv[4];
            float rs = 0.f;
            #pragma unroll
            for (int j = 0; j < 4; j++) {
                pv[j] = (s[i][j] < -1e29f) ? 0.f : __expf(s[i][j] - mnew);
                rs += pv[j];
            }
            rs += __shfl_xor_sync(0xffffffffu, rs, 1);
            rs += __shfl_xor_sync(0xffffffffu, rs, 2);
            rs += __shfl_xor_sync(0xffffffffu, rs, 4);
            rs += __shfl_xor_sync(0xffffffffu, rs, 8);
            mrow[i] = mnew;
            lrow[i] = lrow[i] * fac + rs;
            #pragma unroll
            for (int j = 0; j < 4; j++) accO[i][j] *= fac;
            #pragma unroll
            for (int j = 0; j < 4; j++)
                Ps[(ty * 4 + i) * SM_STRIDE + tx * 4 + j] = pv[j];
        }
        __syncthreads();

        #pragma unroll 8
        for (int kk = 0; kk < 64; kk++) {
            float a[4], b[4];
            #pragma unroll
            for (int i = 0; i < 4; i++) a[i] = Ps[(ty * 4 + i) * SM_STRIDE + kk];
            #pragma unroll
            for (int j = 0; j < 4; j++) b[j] = Vs[kk * SM_STRIDE + tx * 4 + j];
            #pragma unroll
            for (int i = 0; i < 4; i++)
                #pragma unroll
                for (int j = 0; j < 4; j++)
                    accO[i][j] = fmaf(a[i], b[j], accO[i][j]);
        }
        __syncthreads();
    }

    const int b = bh >> 4, h = bh & 15;
    #pragma unroll
    for (int i = 0; i < 4; i++) {
        int sp = q0 + ty * 4 + i;
        float inv = 1.f / lrow[i];
        float4 o4 = make_float4(accO[i][0] * inv, accO[i][1] * inv,
                                accO[i][2] * inv, accO[i][3] * inv);
        *reinterpret_cast<float4*>(
            &g_ctx[((size_t)(b * SS + sp)) * EE + h * DD + tx * 4]) = o4;
    }
}

extern "C" void kernel_launch(void* const* d_in, const int* in_sizes, int n_in,
                              void* d_out, int out_size)
{
    (void)in_sizes; (void)n_in; (void)out_size;
    const float* x  = (const float*)d_in[0];
    const float* Wq = (const float*)d_in[1];
    const float* bq = (const float*)d_in[2];
    const float* Wk = (const float*)d_in[3];
    const float* bk = (const float*)d_in[4];
    const float* Wv = (const float*)d_in[5];
    const float* bv = (const float*)d_in[6];
    const float* Wo = (const float*)d_in[7];
    const float* bo = (const float*)d_in[8];
    float* out = (float*)d_out;

    cudaFuncSetAttribute(proj_mma<0>, cudaFuncAttributeMaxDynamicSharedMemorySize, SMEM_PROJ);
    cudaFuncSetAttribute(proj_mma<1>, cudaFuncAttributeMaxDynamicSharedMemorySize, SMEM_PROJ);
    cudaFuncSetAttribute(attn_kernel, cudaFuncAttributeMaxDynamicSharedMemorySize, SMEM_ATTN);

    dim3 gq(EE / 128, MM / 128, 3);
    proj_mma<0><<<gq, 256, SMEM_PROJ>>>(x, Wq, Wk, Wv, bq, bk, bv, nullptr);

    attn_kernel<<<dim3(4, 16, BB * HH), 256, SMEM_ATTN>>>();

    dim3 go(EE / 128, MM / 128, 1);
    proj_mma<1><<<go, 256, SMEM_PROJ>>>(nullptr, Wo, nullptr, nullptr, bo, nullptr, nullptr, out);
}

// round 5
// speedup vs baseline: 2.9327x; 1.0027x over previous
#include <cuda_runtime.h>
#include <math.h>
#include <stdint.h>

#define BB 2
#define SS 4096
#define EE 1024
#define HH 16
#define DD 64
#define WIN_ 256
#define MM (BB*SS)   // 8192

// scratch (allocation-free: __device__ globals)
static __device__ float g_q[(size_t)BB*HH*SS*DD];   // [b][h][s][d], rope'd + scaled
static __device__ float g_k[(size_t)BB*HH*SS*DD];   // [b][h][s][d], rope'd
static __device__ float g_v[(size_t)BB*HH*SS*DD];   // [b][h][s][d]
static __device__ float g_ctx[(size_t)MM*EE];       // [b][s][e]

// rope over the HEAD axis: angle = head_idx * 10000^{-(j%32)/32}, interleaved rotation
__device__ __forceinline__ void rope_pair(float& v0, float& v1, int h, int j) {
    const float C = 0.28782313662425572f; // ln(10000)/32
    float invA = __expf(-(float)( j      & 31) * C);
    float invB = __expf(-(float)((j + 1) & 31) * C);
    float sa, ca, sb, cb;
    __sincosf((float)h * invA, &sa, &ca);
    __sincosf((float)h * invB, &sb, &cb);
    float r0 = v0 * ca - v1 * sa;
    float r1 = v1 * cb + v0 * sb;
    v0 = r0; v1 = r1;
}

__device__ __forceinline__ uint32_t f2tf(float f) {
    uint32_t u;
    asm("cvt.rna.tf32.f32 %0, %1;" : "=r"(u) : "f"(f));
    return u;
}

__device__ __forceinline__ void mma_tf32(float (&c)[4], const uint32_t (&a)[4], const uint32_t (&b)[2]) {
    asm volatile(
        "mma.sync.aligned.m16n8k8.row.col.f32.tf32.tf32.f32 "
        "{%0,%1,%2,%3},{%4,%5,%6,%7},{%8,%9},{%0,%1,%2,%3};"
        : "+f"(c[0]), "+f"(c[1]), "+f"(c[2]), "+f"(c[3])
        : "r"(a[0]), "r"(a[1]), "r"(a[2]), "r"(a[3]), "r"(b[0]), "r"(b[1]));
}

// ---------------- projection GEMM (TF32 tensor cores): out = X @ W^T + b ----------------
// MODE 0: X = x, z selects (Wq,Wk,Wv); rope epilogue; writes g_q/g_k/g_v [b,h,s,d]
// MODE 1: X = g_ctx, W0 = Wo; writes d_out [m,n]
#define ASTRIDE 36                              // floats; stride 36 -> frag LDS conflict-free
#define SMEM_PROJ (4 * 128 * ASTRIDE * 4)       // 2 stages x (A + B) tiles = 73728 B

template<int MODE>
__global__ __launch_bounds__(256)
void proj_mma(const float* __restrict__ X,
              const float* __restrict__ W0, const float* __restrict__ W1,
              const float* __restrict__ W2,
              const float* __restrict__ b0, const float* __restrict__ b1,
              const float* __restrict__ b2,
              float* __restrict__ out)
{
    extern __shared__ uint32_t sm_u[];
    uint32_t* As = sm_u;                       // [2][128][ASTRIDE]
    uint32_t* Bs = sm_u + 2 * 128 * ASTRIDE;   // [2][128][ASTRIDE]

    const int z = blockIdx.z;
    const float* A    = (MODE == 1) ? (const float*)g_ctx : X;
    const float* W    = (MODE == 1) ? W0 : (z == 0 ? W0 : (z == 1 ? W1 : W2));
    const float* bias = (MODE == 1) ? b0 : (z == 0 ? b0 : (z == 1 ? b1 : b2));

    const int tid   = threadIdx.x;
    const int lane  = tid & 31;
    const int warp  = tid >> 5;
    const int warpM = warp >> 2;               // 0..1 -> 64-row slab
    const int warpN = warp & 3;                // 0..3 -> 32-col slab
    const int grp   = lane >> 2;               // 0..7
    const int qid   = lane & 3;                // 0..3
    const int mBase = blockIdx.y * 128;
    const int nBase = blockIdx.x * 128;

    const int ldRow = tid >> 3;                // 0..31
    const int ldCol = (tid & 7) * 4;           // 0..28

    float4 ra[4], rb[4];

    // prologue: load k-slab 0
    #pragma unroll
    for (int p = 0; p < 4; p++) {
        ra[p] = *reinterpret_cast<const float4*>(&A[(size_t)(mBase + ldRow + p * 32) * EE + ldCol]);
        rb[p] = *reinterpret_cast<const float4*>(&W[(size_t)(nBase + ldRow + p * 32) * EE + ldCol]);
    }
    #pragma unroll
    for (int p = 0; p < 4; p++) {
        int r = ldRow + p * 32;
        uint4 ua = make_uint4(f2tf(ra[p].x), f2tf(ra[p].y), f2tf(ra[p].z), f2tf(ra[p].w));
        uint4 ub = make_uint4(f2tf(rb[p].x), f2tf(rb[p].y), f2tf(rb[p].z), f2tf(rb[p].w));
        *reinterpret_cast<uint4*>(&As[r * ASTRIDE + ldCol]) = ua;
        *reinterpret_cast<uint4*>(&Bs[r * ASTRIDE + ldCol]) = ub;
    }
    __syncthreads();

    float acc[4][4][4];
    #pragma unroll
    for (int mf = 0; mf < 4; mf++)
        #pragma unroll
        for (int nf = 0; nf < 4; nf++)
            #pragma unroll
            for (int r = 0; r < 4; r++) acc[mf][nf][r] = 0.f;

    const int NIT = EE / 32;   // 32
    for (int k0 = 0; k0 < NIT; k0++) {
        const int cur = k0 & 1;
        const bool more = (k0 + 1 < NIT);
        if (more) {
            int kofs = (k0 + 1) * 32 + ldCol;
            #pragma unroll
            for (int p = 0; p < 4; p++) {
                ra[p] = *reinterpret_cast<const float4*>(&A[(size_t)(mBase + ldRow + p * 32) * EE + kofs]);
                rb[p] = *reinterpret_cast<const float4*>(&W[(size_t)(nBase + ldRow + p * 32) * EE + kofs]);
            }
        }

        const uint32_t* Ac = As + cur * 128 * ASTRIDE;
        const uint32_t* Bc = Bs + cur * 128 * ASTRIDE;

        #pragma unroll
        for (int ks = 0; ks < 4; ks++) {
            uint32_t af[4][4];
            #pragma unroll
            for (int mf = 0; mf < 4; mf++) {
                int base = (warpM * 64 + mf * 16 + grp) * ASTRIDE + ks * 8 + qid;
                af[mf][0] = Ac[base];
                af[mf][1] = Ac[base + 8 * ASTRIDE];
                af[mf][2] = Ac[base + 4];
                af[mf][3] = Ac[base + 8 * ASTRIDE + 4];
            }
            uint32_t bf[4][2];
            #pragma unroll
            for (int nf = 0; nf < 4; nf++) {
                int base = (warpN * 32 + nf * 8 + grp) * ASTRIDE + ks * 8 + qid;
                bf[nf][0] = Bc[base];
                bf[nf][1] = Bc[base + 4];
            }
            #pragma unroll
            for (int mf = 0; mf < 4; mf++)
                #pragma unroll
                for (int nf = 0; nf < 4; nf++)
                    mma_tf32(acc[mf][nf], af[mf], bf[nf]);
        }

        if (more) {
            const int nxt = (k0 + 1) & 1;
            uint32_t* An = As + nxt * 128 * ASTRIDE;
            uint32_t* Bn = Bs + nxt * 128 * ASTRIDE;
            #pragma unroll
            for (int p = 0; p < 4; p++) {
                int r = ldRow + p * 32;
                uint4 ua = make_uint4(f2tf(ra[p].x), f2tf(ra[p].y), f2tf(ra[p].z), f2tf(ra[p].w));
                uint4 ub = make_uint4(f2tf(rb[p].x), f2tf(rb[p].y), f2tf(rb[p].z), f2tf(rb[p].w));
                *reinterpret_cast<uint4*>(&An[r * ASTRIDE + ldCol]) = ua;
                *reinterpret_cast<uint4*>(&Bn[r * ASTRIDE + ldCol]) = ub;
            }
        }
        __syncthreads();
    }

    // epilogue: bias (+rope/scale for MODE 0), scatter
    #pragma unroll
    for (int mf = 0; mf < 4; mf++) {
        #pragma unroll
        for (int half = 0; half < 2; half++) {
            int row = mBase + warpM * 64 + mf * 16 + grp + half * 8;
            int bb   = row >> 12;
            int srow = row & 4095;
            #pragma unroll
            for (int nf = 0; nf < 4; nf++) {
                int col = nBase + warpN * 32 + nf * 8 + qid * 2;
                float v0 = acc[mf][nf][half * 2 + 0] + bias[col];
                float v1 = acc[mf][nf][half * 2 + 1] + bias[col + 1];
                if (MODE == 1) {
                    *reinterpret_cast<float2*>(&out[(size_t)row * EE + col]) = make_float2(v0, v1);
                } else {
                    int h = col >> 6;
                    int j = col & 63;     // even
                    if (z <= 1) rope_pair(v0, v1, h, j);
                    if (z == 0) { v0 *= 0.125f; v1 *= 0.125f; }
                    float* dst = (z == 0) ? g_q : (z == 1) ? g_k : g_v;
                    size_t idx = (((size_t)bb * HH + h) * SS + srow) * DD + j;
                    *reinterpret_cast<float2*>(&dst[idx]) = make_float2(v0, v1);
                }
            }
        }
    }
}

// ---------------- sliding-window attention (flash-style, fp32 SIMT) ----------------
#define SM_STRIDE 65
#define SMEM_ATTN (4 * 64 * SM_STRIDE * (int)sizeof(float))

__global__ __launch_bounds__(256)
void attn_kernel()
{
    extern __shared__ float smx[];
    float* Qs = smx;
    float* Ks = smx + 1 * 64 * SM_STRIDE;
    float* Vs = smx + 2 * 64 * SM_STRIDE;
    float* Ps = smx + 3 * 64 * SM_STRIDE;

    const int qb = blockIdx.x;
    const int c  = blockIdx.y;
    const int bh = blockIdx.z;
    const int tid = threadIdx.x;
    const int tx = tid & 15, ty = tid >> 4;

    const float* Qg = g_q + (size_t)bh * SS * DD;
    const float* Kg = g_k + (size_t)bh * SS * DD;
    const float* Vg = g_v + (size_t)bh * SS * DD;

    const int q0 = c * WIN_ + qb * 64;

    #pragma unroll
    for (int p = 0; p < 4; p++) {
        int o = tid * 4 + p * 1024;
        int r = o >> 6, dc = o & 63;
        float4 v = *reinterpret_cast<const float4*>(&Qg[(size_t)(q0 + r) * DD + dc]);
        Qs[r * SM_STRIDE + dc + 0] = v.x;
        Qs[r * SM_STRIDE + dc + 1] = v.y;
        Qs[r * SM_STRIDE + dc + 2] = v.z;
        Qs[r * SM_STRIDE + dc + 3] = v.w;
    }

    float accO[4][4];
    float mrow[4], lrow[4];
    #pragma unroll
    for (int i = 0; i < 4; i++) {
        mrow[i] = -1e30f; lrow[i] = 0.f;
        #pragma unroll
        for (int j = 0; j < 4; j++) accO[i][j] = 0.f;
    }

    for (int kt = qb; kt <= qb + 8; kt++) {
        const int kbase = c * WIN_ - WIN_ + kt * 64;
        if (kbase >= SS || kbase + 63 < 0) continue;

        #pragma unroll
        for (int p = 0; p < 4; p++) {
            int o = tid * 4 + p * 1024;
            int r = o >> 6, dc = o & 63;
            int kp = kbase + r;
            float4 kv = *reinterpret_cast<const float4*>(&Kg[(size_t)kp * DD + dc]);
            float4 vv = *reinterpret_cast<const float4*>(&Vg[(size_t)kp * DD + dc]);
            Ks[r * SM_STRIDE + dc + 0] = kv.x; Ks[r * SM_STRIDE + dc + 1] = kv.y;
            Ks[r * SM_STRIDE + dc + 2] = kv.z; Ks[r * SM_STRIDE + dc + 3] = kv.w;
            Vs[r * SM_STRIDE + dc + 0] = vv.x; Vs[r * SM_STRIDE + dc + 1] = vv.y;
            Vs[r * SM_STRIDE + dc + 2] = vv.z; Vs[r * SM_STRIDE + dc + 3] = vv.w;
        }
        __syncthreads();

        float s[4][4];
        #pragma unroll
        for (int i = 0; i < 4; i++)
            #pragma unroll
            for (int j = 0; j < 4; j++) s[i][j] = 0.f;

        #pragma unroll 8
        for (int dd = 0; dd < 64; dd++) {
            float a[4], b[4];
            #pragma unroll
            for (int i = 0; i < 4; i++) a[i] = Qs[(ty * 4 + i) * SM_STRIDE + dd];
            #pragma unroll
            for (int j = 0; j < 4; j++) b[j] = Ks[(tx * 4 + j) * SM_STRIDE + dd];
            #pragma unroll
            for (int i = 0; i < 4; i++)
                #pragma unroll
                for (int j = 0; j < 4; j++)
                    s[i][j] = fmaf(a[i], b[j], s[i][j]);
        }

        #pragma unroll
        for (int i = 0; i < 4; i++) {
            int qp = q0 + ty * 4 + i;
            float mx = -1e30f;
            #pragma unroll
            for (int j = 0; j < 4; j++) {
                int kp = kbase + tx * 4 + j;
                bool ok = (kp >= qp - WIN_) && (kp <= qp + WIN_);
                s[i][j] = ok ? s[i][j] : -1e30f;
                mx = fmaxf(mx, s[i][j]);
            }
            mx = fmaxf(mx, __shfl_xor_sync(0xffffffffu, mx, 1));
            mx = fmaxf(mx, __shfl_xor_sync(0xffffffffu, mx, 2));
            mx = fmaxf(mx, __shfl_xor_sync(0xffffffffu, mx, 4));
            mx = fmaxf(mx, __shfl_xor_sync(0xffffffffu, mx, 8));
            float mnew = fmaxf(mrow[i], mx);
            float fac = __expf(mrow[i] - mnew);
            float pv[4];
            float rs = 0.f;
            #pragma unroll
            for (int j = 0; j < 4; j++) {
                pv[j] = (s[i][j] < -1e29f) ? 0.f : __expf(s[i][j] - mnew);
                rs += pv[j];
            }
            rs += __shfl_xor_sync(0xffffffffu, rs, 1);
            rs += __shfl_xor_sync(0xffffffffu, rs, 2);
            rs += __shfl_xor_sync(0xffffffffu, rs, 4);
            rs += __shfl_xor_sync(0xffffffffu, rs, 8);
            mrow[i] = mnew;
            lrow[i] = lrow[i] * fac + rs;
            #pragma unroll
            for (int j = 0; j < 4; j++) accO[i][j] *= fac;
            #pragma unroll
            for (int j = 0; j < 4; j++)
                Ps[(ty * 4 + i) * SM_STRIDE + tx * 4 + j] = pv[j];
        }
        __syncthreads();

        #pragma unroll 8
        for (int kk = 0; kk < 64; kk++) {
            float a[4], b[4];
            #pragma unroll
            for (int i = 0; i < 4; i++) a[i] = Ps[(ty * 4 + i) * SM_STRIDE + kk];
            #pragma unroll
            for (int j = 0; j < 4; j++) b[j] = Vs[kk * SM_STRIDE + tx * 4 + j];
            #pragma unroll
            for (int i = 0; i < 4; i++)
                #pragma unroll
                for (int j = 0; j < 4; j++)
                    accO[i][j] = fmaf(a[i], b[j], accO[i][j]);
        }
        __syncthreads();
    }

    const int b = bh >> 4, h = bh & 15;
    #pragma unroll
    for (int i = 0; i < 4; i++) {
        int sp = q0 + ty * 4 + i;
        float inv = 1.f / lrow[i];
        float4 o4 = make_float4(accO[i][0] * inv, accO[i][1] * inv,
                                accO[i][2] * inv, accO[i][3] * inv);
        *reinterpret_cast<float4*>(
            &g_ctx[((size_t)(b * SS + sp)) * EE + h * DD + tx * 4]) = o4;
    }
}

extern "C" void kernel_launch(void* const* d_in, const int* in_sizes, int n_in,
                              void* d_out, int out_size)
{
    (void)in_sizes; (void)n_in; (void)out_size;
    const float* x  = (const float*)d_in[0];
    const float* Wq = (const float*)d_in[1];
    const float* bq = (const float*)d_in[2];
    const float* Wk = (const float*)d_in[3];
    const float* bk = (const float*)d_in[4];
    const float* Wv = (const float*)d_in[5];
    const float* bv = (const float*)d_in[6];
    const float* Wo = (const float*)d_in[7];
    const float* bo = (const float*)d_in[8];
    float* out = (float*)d_out;

    cudaFuncSetAttribute(proj_mma<0>, cudaFuncAttributeMaxDynamicSharedMemorySize, SMEM_PROJ);
    cudaFuncSetAttribute(proj_mma<1>, cudaFuncAttributeMaxDynamicSharedMemorySize, SMEM_PROJ);
    cudaFuncSetAttribute(attn_kernel, cudaFuncAttributeMaxDynamicSharedMemorySize, SMEM_ATTN);

    dim3 gq(EE / 128, MM / 128, 3);
    proj_mma<0><<<gq, 256, SMEM_PROJ>>>(x, Wq, Wk, Wv, bq, bk, bv, nullptr);

    attn_kernel<<<dim3(4, 16, BB * HH), 256, SMEM_ATTN>>>();

    dim3 go(EE / 128, MM / 128, 1);
    proj_mma<1><<<go, 256, SMEM_PROJ>>>(nullptr, Wo, nullptr, nullptr, bo, nullptr, nullptr, out);
}

// round 7
// speedup vs baseline: 4.4663x; 1.5229x over previous
#include <cuda_runtime.h>
#include <math.h>
#include <stdint.h>

#define BB 2
#define SS 4096
#define EE 1024
#define HH 16
#define DD 64
#define WIN_ 256
#define MM (BB*SS)   // 8192

// scratch (allocation-free: __device__ globals)
// q/k/v hold tf32 bit patterns (fp32 with low mantissa zeroed), ready for mma
static __device__ uint32_t g_q[(size_t)BB*HH*SS*DD];   // [b][h][s][d], rope'd + scaled, tf32
static __device__ uint32_t g_k[(size_t)BB*HH*SS*DD];   // [b][h][s][d], rope'd, tf32
static __device__ uint32_t g_v[(size_t)BB*HH*SS*DD];   // [b][h][s][d], tf32
static __device__ float    g_ctx[(size_t)MM*EE];       // [b][s][e], fp32

// rope over the HEAD axis: angle = head_idx * 10000^{-(j%32)/32}, interleaved rotation
__device__ __forceinline__ void rope_pair(float& v0, float& v1, int h, int j) {
    const float C = 0.28782313662425572f; // ln(10000)/32
    float invA = __expf(-(float)( j      & 31) * C);
    float invB = __expf(-(float)((j + 1) & 31) * C);
    float sa, ca, sb, cb;
    __sincosf((float)h * invA, &sa, &ca);
    __sincosf((float)h * invB, &sb, &cb);
    float r0 = v0 * ca - v1 * sa;
    float r1 = v1 * cb + v0 * sb;
    v0 = r0; v1 = r1;
}

__device__ __forceinline__ uint32_t f2tf(float f) {
    uint32_t u;
    asm("cvt.rna.tf32.f32 %0, %1;" : "=r"(u) : "f"(f));
    return u;
}

__device__ __forceinline__ void mma_tf32(float (&c)[4], const uint32_t (&a)[4], const uint32_t (&b)[2]) {
    asm volatile(
        "mma.sync.aligned.m16n8k8.row.col.f32.tf32.tf32.f32 "
        "{%0,%1,%2,%3},{%4,%5,%6,%7},{%8,%9},{%0,%1,%2,%3};"
        : "+f"(c[0]), "+f"(c[1]), "+f"(c[2]), "+f"(c[3])
        : "r"(a[0]), "r"(a[1]), "r"(a[2]), "r"(a[3]), "r"(b[0]), "r"(b[1]));
}

// ---------------- projection GEMM (TF32 tensor cores): out = X @ W^T + b ----------------
// MODE 0: X = x, z selects (Wq,Wk,Wv); rope epilogue; writes g_q/g_k/g_v [b,h,s,d] as tf32
// MODE 1: X = g_ctx, W0 = Wo; writes d_out [m,n] fp32
#define ASTRIDE 36                              // floats; stride 36 -> frag LDS conflict-free
#define SMEM_PROJ (4 * 128 * ASTRIDE * 4)       // 2 stages x (A + B) tiles = 73728 B

template<int MODE>
__global__ __launch_bounds__(256)
void proj_mma(const float* __restrict__ X,
              const float* __restrict__ W0, const float* __restrict__ W1,
              const float* __restrict__ W2,
              const float* __restrict__ b0, const float* __restrict__ b1,
              const float* __restrict__ b2,
              float* __restrict__ out)
{
    extern __shared__ uint32_t sm_u[];
    uint32_t* As = sm_u;                       // [2][128][ASTRIDE]
    uint32_t* Bs = sm_u + 2 * 128 * ASTRIDE;   // [2][128][ASTRIDE]

    const int z = blockIdx.z;
    const float* A    = (MODE == 1) ? (const float*)g_ctx : X;
    const float* W    = (MODE == 1) ? W0 : (z == 0 ? W0 : (z == 1 ? W1 : W2));
    const float* bias = (MODE == 1) ? b0 : (z == 0 ? b0 : (z == 1 ? b1 : b2));

    const int tid   = threadIdx.x;
    const int lane  = tid & 31;
    const int warp  = tid >> 5;
    const int warpM = warp >> 2;               // 0..1 -> 64-row slab
    const int warpN = warp & 3;                // 0..3 -> 32-col slab
    const int grp   = lane >> 2;               // 0..7
    const int qid   = lane & 3;                // 0..3
    const int mBase = blockIdx.y * 128;
    const int nBase = blockIdx.x * 128;

    const int ldRow = tid >> 3;                // 0..31
    const int ldCol = (tid & 7) * 4;           // 0..28

    float4 ra[4], rb[4];

    // prologue: load k-slab 0
    #pragma unroll
    for (int p = 0; p < 4; p++) {
        ra[p] = *reinterpret_cast<const float4*>(&A[(size_t)(mBase + ldRow + p * 32) * EE + ldCol]);
        rb[p] = *reinterpret_cast<const float4*>(&W[(size_t)(nBase + ldRow + p * 32) * EE + ldCol]);
    }
    #pragma unroll
    for (int p = 0; p < 4; p++) {
        int r = ldRow + p * 32;
        uint4 ua = make_uint4(f2tf(ra[p].x), f2tf(ra[p].y), f2tf(ra[p].z), f2tf(ra[p].w));
        uint4 ub = make_uint4(f2tf(rb[p].x), f2tf(rb[p].y), f2tf(rb[p].z), f2tf(rb[p].w));
        *reinterpret_cast<uint4*>(&As[r * ASTRIDE + ldCol]) = ua;
        *reinterpret_cast<uint4*>(&Bs[r * ASTRIDE + ldCol]) = ub;
    }
    __syncthreads();

    float acc[4][4][4];
    #pragma unroll
    for (int mf = 0; mf < 4; mf++)
        #pragma unroll
        for (int nf = 0; nf < 4; nf++)
            #pragma unroll
            for (int r = 0; r < 4; r++) acc[mf][nf][r] = 0.f;

    const int NIT = EE / 32;   // 32
    for (int k0 = 0; k0 < NIT; k0++) {
        const int cur = k0 & 1;
        const bool more = (k0 + 1 < NIT);
        if (more) {
            int kofs = (k0 + 1) * 32 + ldCol;
            #pragma unroll
            for (int p = 0; p < 4; p++) {
                ra[p] = *reinterpret_cast<const float4*>(&A[(size_t)(mBase + ldRow + p * 32) * EE + kofs]);
                rb[p] = *reinterpret_cast<const float4*>(&W[(size_t)(nBase + ldRow + p * 32) * EE + kofs]);
            }
        }

        const uint32_t* Ac = As + cur * 128 * ASTRIDE;
        const uint32_t* Bc = Bs + cur * 128 * ASTRIDE;

        #pragma unroll
        for (int ks = 0; ks < 4; ks++) {
            uint32_t af[4][4];
            #pragma unroll
            for (int mf = 0; mf < 4; mf++) {
                int base = (warpM * 64 + mf * 16 + grp) * ASTRIDE + ks * 8 + qid;
                af[mf][0] = Ac[base];
                af[mf][1] = Ac[base + 8 * ASTRIDE];
                af[mf][2] = Ac[base + 4];
                af[mf][3] = Ac[base + 8 * ASTRIDE + 4];
            }
            uint32_t bf[4][2];
            #pragma unroll
            for (int nf = 0; nf < 4; nf++) {
                int base = (warpN * 32 + nf * 8 + grp) * ASTRIDE + ks * 8 + qid;
                bf[nf][0] = Bc[base];
                bf[nf][1] = Bc[base + 4];
            }
            #pragma unroll
            for (int mf = 0; mf < 4; mf++)
                #pragma unroll
                for (int nf = 0; nf < 4; nf++)
                    mma_tf32(acc[mf][nf], af[mf], bf[nf]);
        }

        if (more) {
            const int nxt = (k0 + 1) & 1;
            uint32_t* An = As + nxt * 128 * ASTRIDE;
            uint32_t* Bn = Bs + nxt * 128 * ASTRIDE;
            #pragma unroll
            for (int p = 0; p < 4; p++) {
                int r = ldRow + p * 32;
                uint4 ua = make_uint4(f2tf(ra[p].x), f2tf(ra[p].y), f2tf(ra[p].z), f2tf(ra[p].w));
                uint4 ub = make_uint4(f2tf(rb[p].x), f2tf(rb[p].y), f2tf(rb[p].z), f2tf(rb[p].w));
                *reinterpret_cast<uint4*>(&An[r * ASTRIDE + ldCol]) = ua;
                *reinterpret_cast<uint4*>(&Bn[r * ASTRIDE + ldCol]) = ub;
            }
        }
        __syncthreads();
    }

    // epilogue: bias (+rope/scale for MODE 0), scatter
    #pragma unroll
    for (int mf = 0; mf < 4; mf++) {
        #pragma unroll
        for (int half = 0; half < 2; half++) {
            int row = mBase + warpM * 64 + mf * 16 + grp + half * 8;
            int bb   = row >> 12;
            int srow = row & 4095;
            #pragma unroll
            for (int nf = 0; nf < 4; nf++) {
                int col = nBase + warpN * 32 + nf * 8 + qid * 2;
                float v0 = acc[mf][nf][half * 2 + 0] + bias[col];
                float v1 = acc[mf][nf][half * 2 + 1] + bias[col + 1];
                if (MODE == 1) {
                    *reinterpret_cast<float2*>(&out[(size_t)row * EE + col]) = make_float2(v0, v1);
                } else {
                    int h = col >> 6;
                    int j = col & 63;     // even
                    if (z <= 1) rope_pair(v0, v1, h, j);
                    if (z == 0) { v0 *= 0.125f; v1 *= 0.125f; }
                    uint32_t* dst = (z == 0) ? g_q : (z == 1) ? g_k : g_v;
                    size_t idx = (((size_t)bb * HH + h) * SS + srow) * DD + j;
                    *reinterpret_cast<uint2*>(&dst[idx]) = make_uint2(f2tf(v0), f2tf(v1));
                }
            }
        }
    }
}

// ---------------- sliding-window attention (flash-style, TF32 tensor cores) ----------------
// grid (qb=4, c=16, bh=32); block 128 (4 warps); each warp owns 16 query rows.
#define AST 68                                   // smem stride (uint32); mod 32 == 4 -> conflict-free frags
#define SMEM_ATTN (3 * 64 * AST * 4)             // Qs(->Ps) + Ks + Vs = 52224 B

__global__ __launch_bounds__(128)
void attn_mma_kernel()
{
    extern __shared__ uint32_t sm[];
    uint32_t* Qs = sm;                  // 64 x AST (reused as Ps after Q frags are in regs)
    uint32_t* Ks = sm + 64 * AST;
    uint32_t* Vs = sm + 2 * 64 * AST;
    float*    Ps = reinterpret_cast<float*>(Qs);

    const int qb = blockIdx.x;
    const int c  = blockIdx.y;
    const int bh = blockIdx.z;
    const int tid  = threadIdx.x;
    const int w    = tid >> 5;
    const int lane = tid & 31;
    const int grp  = lane >> 2;          // 0..7
    const int qid  = lane & 3;           // 0..3

    const uint32_t* Qg = g_q + (size_t)bh * SS * DD;
    const uint32_t* Kg = g_k + (size_t)bh * SS * DD;
    const uint32_t* Vg = g_v + (size_t)bh * SS * DD;

    const int q0 = c * WIN_ + qb * 64;

    // load 64x64 Q tile (coalesced), then build A fragments in registers
    {
        int r0 = tid >> 4;
        int dc = (tid & 15) * 4;
        #pragma unroll
        for (int p = 0; p < 8; p++) {
            int r = r0 + p * 8;
            *reinterpret_cast<uint4*>(&Qs[r * AST + dc]) =
                *reinterpret_cast<const uint4*>(&Qg[(size_t)(q0 + r) * DD + dc]);
        }
    }
    __syncthreads();

    uint32_t qf[8][4];
    {
        int r = w * 16 + grp;
        #pragma unroll
        for (int ks = 0; ks < 8; ks++) {
            qf[ks][0] = Qs[r * AST + ks * 8 + qid];
            qf[ks][1] = Qs[(r + 8) * AST + ks * 8 + qid];
            qf[ks][2] = Qs[r * AST + ks * 8 + qid + 4];
            qf[ks][3] = Qs[(r + 8) * AST + ks * 8 + qid + 4];
        }
    }
    // (Ps overwrites Qs only after the K/V-load __syncthreads below — safe.)

    float o[8][4];
    #pragma unroll
    for (int nf = 0; nf < 8; nf++)
        #pragma unroll
        for (int r = 0; r < 4; r++) o[nf][r] = 0.f;
    float m0 = -1e30f, m1 = -1e30f, l0 = 0.f, l1 = 0.f;

    const int qp0 = q0 + w * 16 + grp;
    const int qp1 = qp0 + 8;

    for (int kt = qb; kt <= qb + 8; kt++) {
        const int kbase = c * WIN_ - WIN_ + kt * 64;
        if (kbase >= SS || kbase < 0) continue;     // 64-aligned tiles: fully in or out

        // cooperative K/V tile load
        {
            int r0 = tid >> 4;
            int dc = (tid & 15) * 4;
            #pragma unroll
            for (int p = 0; p < 8; p++) {
                int r = r0 + p * 8;
                *reinterpret_cast<uint4*>(&Ks[r * AST + dc]) =
                    *reinterpret_cast<const uint4*>(&Kg[(size_t)(kbase + r) * DD + dc]);
                *reinterpret_cast<uint4*>(&Vs[r * AST + dc]) =
                    *reinterpret_cast<const uint4*>(&Vg[(size_t)(kbase + r) * DD + dc]);
            }
        }
        __syncthreads();

        // S = Q K^T : 8 n-frags of m16n8, accumulate over 8 k-steps
        float s[8][4];
        #pragma unroll
        for (int nf = 0; nf < 8; nf++)
            #pragma unroll
            for (int r = 0; r < 4; r++) s[nf][r] = 0.f;

        #pragma unroll
        for (int ks = 0; ks < 8; ks++) {
            #pragma unroll
            for (int nf = 0; nf < 8; nf++) {
                uint32_t b[2];
                int base = (nf * 8 + grp) * AST + ks * 8 + qid;
                b[0] = Ks[base];
                b[1] = Ks[base + 4];
                mma_tf32(s[nf], qf[ks], b);
            }
        }

        // mask + online softmax in C-fragment layout
        float nm0 = m0, nm1 = m1;
        #pragma unroll
        for (int nf = 0; nf < 8; nf++) {
            int kp = kbase + nf * 8 + qid * 2;
            s[nf][0] = (kp     >= qp0 - WIN_ && kp     <= qp0 + WIN_) ? s[nf][0] : -1e30f;
            s[nf][1] = (kp + 1 >= qp0 - WIN_ && kp + 1 <= qp0 + WIN_) ? s[nf][1] : -1e30f;
            s[nf][2] = (kp     >= qp1 - WIN_ && kp     <= qp1 + WIN_) ? s[nf][2] : -1e30f;
            s[nf][3] = (kp + 1 >= qp1 - WIN_ && kp + 1 <= qp1 + WIN_) ? s[nf][3] : -1e30f;
            nm0 = fmaxf(nm0, fmaxf(s[nf][0], s[nf][1]));
            nm1 = fmaxf(nm1, fmaxf(s[nf][2], s[nf][3]));
        }
        nm0 = fmaxf(nm0, __shfl_xor_sync(0xffffffffu, nm0, 1));
        nm0 = fmaxf(nm0, __shfl_xor_sync(0xffffffffu, nm0, 2));
        nm1 = fmaxf(nm1, __shfl_xor_sync(0xffffffffu, nm1, 1));
        nm1 = fmaxf(nm1, __shfl_xor_sync(0xffffffffu, nm1, 2));

        float fac0 = __expf(m0 - nm0);
        float fac1 = __expf(m1 - nm1);
        m0 = nm0; m1 = nm1;

        float rs0 = 0.f, rs1 = 0.f;
        const int prow0 = (w * 16 + grp) * AST + qid * 2;
        const int prow1 = (w * 16 + grp + 8) * AST + qid * 2;
        #pragma unroll
        for (int nf = 0; nf < 8; nf++) {
            // round P to tf32 BEFORE summing so l matches what the MMA multiplies
            uint32_t u00 = f2tf(__expf(s[nf][0] - m0));
            uint32_t u01 = f2tf(__expf(s[nf][1] - m0));
            uint32_t u10 = f2tf(__expf(s[nf][2] - m1));
            uint32_t u11 = f2tf(__expf(s[nf][3] - m1));
            rs0 += __uint_as_float(u00) + __uint_as_float(u01);
            rs1 += __uint_as_float(u10) + __uint_as_float(u11);
            *reinterpret_cast<uint2*>(&Ps[prow0 + nf * 8]) = make_uint2(u00, u01);
            *reinterpret_cast<uint2*>(&Ps[prow1 + nf * 8]) = make_uint2(u10, u11);
        }
        rs0 += __shfl_xor_sync(0xffffffffu, rs0, 1);
        rs0 += __shfl_xor_sync(0xffffffffu, rs0, 2);
        rs1 += __shfl_xor_sync(0xffffffffu, rs1, 1);
        rs1 += __shfl_xor_sync(0xffffffffu, rs1, 2);
        l0 = l0 * fac0 + rs0;
        l1 = l1 * fac1 + rs1;

        #pragma unroll
        for (int nf = 0; nf < 8; nf++) {
            o[nf][0] *= fac0; o[nf][1] *= fac0;
            o[nf][2] *= fac1; o[nf][3] *= fac1;
        }
        // Ps rows are warp-private: no cross-warp sync needed before PV.

        // O += P @ V
        #pragma unroll
        for (int ks = 0; ks < 8; ks++) {
            uint32_t a[4];
            int abase = (w * 16 + grp) * AST + ks * 8 + qid;
            a[0] = __float_as_uint(Ps[abase]);
            a[1] = __float_as_uint(Ps[abase + 8 * AST]);
            a[2] = __float_as_uint(Ps[abase + 4]);
            a[3] = __float_as_uint(Ps[abase + 8 * AST + 4]);
            #pragma unroll
            for (int nf = 0; nf < 8; nf++) {
                uint32_t b[2];
                int vbase = (ks * 8 + qid) * AST + nf * 8 + grp;
                b[0] = Vs[vbase];
                b[1] = Vs[vbase + 4 * AST];
                mma_tf32(o[nf], a, b);
            }
        }
        __syncthreads();   // before next K/V overwrite
    }

    // epilogue: normalize + write ctx (fp32)
    const int b = bh >> 4, h = bh & 15;
    float inv0 = 1.f / l0, inv1 = 1.f / l1;
    const int row0 = q0 + w * 16 + grp;
    #pragma unroll
    for (int nf = 0; nf < 8; nf++) {
        int col = h * DD + nf * 8 + qid * 2;
        *reinterpret_cast<float2*>(&g_ctx[((size_t)(b * SS + row0)) * EE + col]) =
            make_float2(o[nf][0] * inv0, o[nf][1] * inv0);
        *reinterpret_cast<float2*>(&g_ctx[((size_t)(b * SS + row0 + 8)) * EE + col]) =
            make_float2(o[nf][2] * inv1, o[nf][3] * inv1);
    }
}

extern "C" void kernel_launch(void* const* d_in, const int* in_sizes, int n_in,
                              void* d_out, int out_size)
{
    (void)in_sizes; (void)n_in; (void)out_size;
    const float* x  = (const float*)d_in[0];
    const float* Wq = (const float*)d_in[1];
    const float* bq = (const float*)d_in[2];
    const float* Wk = (const float*)d_in[3];
    const float* bk = (const float*)d_in[4];
    const float* Wv = (const float*)d_in[5];
    const float* bv = (const float*)d_in[6];
    const float* Wo = (const float*)d_in[7];
    const float* bo = (const float*)d_in[8];
    float* out = (float*)d_out;

    cudaFuncSetAttribute(proj_mma<0>, cudaFuncAttributeMaxDynamicSharedMemorySize, SMEM_PROJ);
    cudaFuncSetAttribute(proj_mma<1>, cudaFuncAttributeMaxDynamicSharedMemorySize, SMEM_PROJ);
    cudaFuncSetAttribute(attn_mma_kernel, cudaFuncAttributeMaxDynamicSharedMemorySize, SMEM_ATTN);

    dim3 gq(EE / 128, MM / 128, 3);
    proj_mma<0><<<gq, 256, SMEM_PROJ>>>(x, Wq, Wk, Wv, bq, bk, bv, nullptr);

    attn_mma_kernel<<<dim3(4, 16, BB * HH), 128, SMEM_ATTN>>>();

    dim3 go(EE / 128, MM / 128, 1);
    proj_mma<1><<<go, 256, SMEM_PROJ>>>(nullptr, Wo, nullptr, nullptr, bo, nullptr, nullptr, out);
}

// round 8
// speedup vs baseline: 4.7923x; 1.0730x over previous
#include <cuda_runtime.h>
#include <math.h>
#include <stdint.h>

#define BB 2
#define SS 4096
#define EE 1024
#define HH 16
#define DD 64
#define WIN_ 256
#define MM (BB*SS)   // 8192

#define XT_ELEMS ((size_t)MM*EE)     // 8388608
#define WT_ELEMS ((size_t)EE*EE)     // 1048576

// scratch (allocation-free: __device__ globals)
// tf32 bit patterns everywhere the tensor cores read
static __device__ uint32_t g_xt[XT_ELEMS];             // x, tf32
static __device__ uint32_t g_wt[4*WT_ELEMS];           // Wq,Wk,Wv,Wo, tf32
static __device__ uint32_t g_q[(size_t)BB*HH*SS*DD];   // [b][h][s][d], rope'd + scaled, tf32
static __device__ uint32_t g_k[(size_t)BB*HH*SS*DD];   // [b][h][s][d], rope'd, tf32
static __device__ uint32_t g_v[(size_t)BB*HH*SS*DD];   // [b][h][s][d], tf32
static __device__ uint32_t g_ctx[(size_t)MM*EE];       // [b][s][e], tf32

// rope over the HEAD axis: angle = head_idx * 10000^{-(j%32)/32}, interleaved rotation
__device__ __forceinline__ void rope_pair(float& v0, float& v1, int h, int j) {
    const float C = 0.28782313662425572f; // ln(10000)/32
    float invA = __expf(-(float)( j      & 31) * C);
    float invB = __expf(-(float)((j + 1) & 31) * C);
    float sa, ca, sb, cb;
    __sincosf((float)h * invA, &sa, &ca);
    __sincosf((float)h * invB, &sb, &cb);
    float r0 = v0 * ca - v1 * sa;
    float r1 = v1 * cb + v0 * sb;
    v0 = r0; v1 = r1;
}

__device__ __forceinline__ uint32_t f2tf(float f) {
    uint32_t u;
    asm("cvt.rna.tf32.f32 %0, %1;" : "=r"(u) : "f"(f));
    return u;
}

__device__ __forceinline__ void mma_tf32(float (&c)[4], const uint32_t (&a)[4], const uint32_t (&b)[2]) {
    asm volatile(
        "mma.sync.aligned.m16n8k8.row.col.f32.tf32.tf32.f32 "
        "{%0,%1,%2,%3},{%4,%5,%6,%7},{%8,%9},{%0,%1,%2,%3};"
        : "+f"(c[0]), "+f"(c[1]), "+f"(c[2]), "+f"(c[3])
        : "r"(a[0]), "r"(a[1]), "r"(a[2]), "r"(a[3]), "r"(b[0]), "r"(b[1]));
}

__device__ __forceinline__ void cp16(uint32_t smem_addr, const void* gptr) {
    asm volatile("cp.async.cg.shared.global [%0], [%1], 16;" :: "r"(smem_addr), "l"(gptr));
}
#define CP_COMMIT() asm volatile("cp.async.commit_group;")
#define CP_WAIT1()  asm volatile("cp.async.wait_group 1;")

// ---------------- one-time tf32 conversion of x and W matrices ----------------
__global__ __launch_bounds__(256)
void conv_kernel(const float* __restrict__ x,
                 const float* __restrict__ wq, const float* __restrict__ wk,
                 const float* __restrict__ wv, const float* __restrict__ wo)
{
    size_t i4 = (size_t)blockIdx.x * 256 + threadIdx.x;
    const size_t x4 = XT_ELEMS / 4;
    const size_t w4 = WT_ELEMS / 4;
    if (i4 >= x4 + 4 * w4) return;
    const float* src; uint32_t* dst; size_t off;
    if (i4 < x4) { src = x; dst = g_xt; off = i4 * 4; }
    else {
        size_t j = i4 - x4;
        int w = (int)(j / w4);
        off = (j - (size_t)w * w4) * 4;
        src = (w == 0) ? wq : (w == 1) ? wk : (w == 2) ? wv : wo;
        dst = g_wt + (size_t)w * WT_ELEMS;
    }
    float4 v = *reinterpret_cast<const float4*>(src + off);
    *reinterpret_cast<uint4*>(dst + off) =
        make_uint4(f2tf(v.x), f2tf(v.y), f2tf(v.z), f2tf(v.w));
}

// ---------------- projection GEMM (TF32, cp.async 3-stage, 256x128 tile) ----------------
// MODE 0: A = g_xt, W = g_wt[z]; rope epilogue; writes g_q/g_k/g_v [b,h,s,d] tf32
// MODE 1: A = g_ctx, W = g_wt[3]; writes d_out [m,n] fp32
#define ASTRIDE 36
#define STAGE_ELEMS ((256 + 128) * ASTRIDE)          // 13824 uint32
#define STAGE_BYTES (STAGE_ELEMS * 4)                // 55296
#define SMEM_PROJ   (3 * STAGE_BYTES)                // 165888

template<int MODE>
__global__ __launch_bounds__(512, 1)
void proj_mma(const float* __restrict__ b0, const float* __restrict__ b1,
              const float* __restrict__ b2, float* __restrict__ out)
{
    extern __shared__ uint32_t sm_u[];
    const uint32_t smem_b = (uint32_t)__cvta_generic_to_shared(sm_u);

    const int z = blockIdx.z;
    const uint32_t* A = (MODE == 1) ? g_ctx : g_xt;
    const uint32_t* W = g_wt + (size_t)((MODE == 1) ? 3 : z) * WT_ELEMS;
    const float* bias = (MODE == 1) ? b0 : (z == 0 ? b0 : (z == 1 ? b1 : b2));

    const int tid   = threadIdx.x;
    const int lane  = tid & 31;
    const int warp  = tid >> 5;            // 0..15
    const int warpM = warp >> 2;           // 0..3 -> 64-row slab
    const int warpN = warp & 3;            // 0..3 -> 32-col slab
    const int grp   = lane >> 2;           // 0..7
    const int qid   = lane & 3;            // 0..3
    const int mBase = blockIdx.y * 256;
    const int nBase = blockIdx.x * 128;

    const int ldRow = tid >> 3;            // 0..63
    const int ldCol = (tid & 7) * 4;       // 0..28

    // async stage loader
    auto issue = [&](int stage, int k0) {
        uint32_t base = smem_b + stage * STAGE_BYTES;
        int kofs = k0 * 32 + ldCol;
        #pragma unroll
        for (int p = 0; p < 4; p++) {
            int r = ldRow + p * 64;
            cp16(base + (uint32_t)(r * ASTRIDE + ldCol) * 4,
                 A + (size_t)(mBase + r) * EE + kofs);
        }
        #pragma unroll
        for (int p = 0; p < 2; p++) {
            int r = ldRow + p * 64;
            cp16(base + (uint32_t)((256 * ASTRIDE) + r * ASTRIDE + ldCol) * 4,
                 W + (size_t)(nBase + r) * EE + kofs);
        }
    };

    float acc[4][4][4];
    #pragma unroll
    for (int mf = 0; mf < 4; mf++)
        #pragma unroll
        for (int nf = 0; nf < 4; nf++)
            #pragma unroll
            for (int r = 0; r < 4; r++) acc[mf][nf][r] = 0.f;

    const int NIT = EE / 32;   // 32
    issue(0, 0); CP_COMMIT();
    issue(1, 1); CP_COMMIT();

    int stage = 0;
    for (int k0 = 0; k0 < NIT; k0++) {
        CP_WAIT1();
        __syncthreads();
        // prefetch k0+2 into the stage computed at k0-1 (safe: everyone passed the sync)
        if (k0 + 2 < NIT) {
            int ns = stage + 2; if (ns >= 3) ns -= 3;
            issue(ns, k0 + 2);
        }
        CP_COMMIT();

        const uint32_t* Ac = sm_u + stage * STAGE_ELEMS;
        const uint32_t* Bc = Ac + 256 * ASTRIDE;

        #pragma unroll
        for (int ks = 0; ks < 4; ks++) {
            uint32_t af[4][4];
            #pragma unroll
            for (int mf = 0; mf < 4; mf++) {
                int base = (warpM * 64 + mf * 16 + grp) * ASTRIDE + ks * 8 + qid;
                af[mf][0] = Ac[base];
                af[mf][1] = Ac[base + 8 * ASTRIDE];
                af[mf][2] = Ac[base + 4];
                af[mf][3] = Ac[base + 8 * ASTRIDE + 4];
            }
            uint32_t bf[4][2];
            #pragma unroll
            for (int nf = 0; nf < 4; nf++) {
                int base = (warpN * 32 + nf * 8 + grp) * ASTRIDE + ks * 8 + qid;
                bf[nf][0] = Bc[base];
                bf[nf][1] = Bc[base + 4];
            }
            #pragma unroll
            for (int mf = 0; mf < 4; mf++)
                #pragma unroll
                for (int nf = 0; nf < 4; nf++)
                    mma_tf32(acc[mf][nf], af[mf], bf[nf]);
        }

        stage++; if (stage >= 3) stage = 0;
    }

    // epilogue: bias (+rope/scale for MODE 0), scatter
    #pragma unroll
    for (int mf = 0; mf < 4; mf++) {
        #pragma unroll
        for (int half = 0; half < 2; half++) {
            int row = mBase + warpM * 64 + mf * 16 + grp + half * 8;
            int bb   = row >> 12;
            int srow = row & 4095;
            #pragma unroll
            for (int nf = 0; nf < 4; nf++) {
                int col = nBase + warpN * 32 + nf * 8 + qid * 2;
                float v0 = acc[mf][nf][half * 2 + 0] + bias[col];
                float v1 = acc[mf][nf][half * 2 + 1] + bias[col + 1];
                if (MODE == 1) {
                    *reinterpret_cast<float2*>(&out[(size_t)row * EE + col]) = make_float2(v0, v1);
                } else {
                    int h = col >> 6;
                    int j = col & 63;     // even
                    if (z <= 1) rope_pair(v0, v1, h, j);
                    if (z == 0) { v0 *= 0.125f; v1 *= 0.125f; }
                    uint32_t* dst = (z == 0) ? g_q : (z == 1) ? g_k : g_v;
                    size_t idx = (((size_t)bb * HH + h) * SS + srow) * DD + j;
                    *reinterpret_cast<uint2*>(&dst[idx]) = make_uint2(f2tf(v0), f2tf(v1));
                }
            }
        }
    }
}

// ---------------- sliding-window attention (flash-style, TF32 tensor cores) ----------------
// grid (qb=4, c=16, bh=32); block 128 (4 warps); each warp owns 16 query rows.
#define AST 68                                   // smem stride (uint32)
#define SMEM_ATTN (3 * 64 * AST * 4)             // Qs(->Ps) + Ks + Vs = 52224 B

__global__ __launch_bounds__(128)
void attn_mma_kernel()
{
    extern __shared__ uint32_t sm[];
    uint32_t* Qs = sm;                  // 64 x AST (reused as Ps after Q frags are in regs)
    uint32_t* Ks = sm + 64 * AST;
    uint32_t* Vs = sm + 2 * 64 * AST;
    float*    Ps = reinterpret_cast<float*>(Qs);

    const int qb = blockIdx.x;
    const int c  = blockIdx.y;
    const int bh = blockIdx.z;
    const int tid  = threadIdx.x;
    const int w    = tid >> 5;
    const int lane = tid & 31;
    const int grp  = lane >> 2;          // 0..7
    const int qid  = lane & 3;           // 0..3

    const uint32_t* Qg = g_q + (size_t)bh * SS * DD;
    const uint32_t* Kg = g_k + (size_t)bh * SS * DD;
    const uint32_t* Vg = g_v + (size_t)bh * SS * DD;

    const int q0 = c * WIN_ + qb * 64;

    {
        int r0 = tid >> 4;
        int dc = (tid & 15) * 4;
        #pragma unroll
        for (int p = 0; p < 8; p++) {
            int r = r0 + p * 8;
            *reinterpret_cast<uint4*>(&Qs[r * AST + dc]) =
                *reinterpret_cast<const uint4*>(&Qg[(size_t)(q0 + r) * DD + dc]);
        }
    }
    __syncthreads();

    uint32_t qf[8][4];
    {
        int r = w * 16 + grp;
        #pragma unroll
        for (int ks = 0; ks < 8; ks++) {
            qf[ks][0] = Qs[r * AST + ks * 8 + qid];
            qf[ks][1] = Qs[(r + 8) * AST + ks * 8 + qid];
            qf[ks][2] = Qs[r * AST + ks * 8 + qid + 4];
            qf[ks][3] = Qs[(r + 8) * AST + ks * 8 + qid + 4];
        }
    }

    float o[8][4];
    #pragma unroll
    for (int nf = 0; nf < 8; nf++)
        #pragma unroll
        for (int r = 0; r < 4; r++) o[nf][r] = 0.f;
    float m0 = -1e30f, m1 = -1e30f, l0 = 0.f, l1 = 0.f;

    const int qp0 = q0 + w * 16 + grp;
    const int qp1 = qp0 + 8;

    for (int kt = qb; kt <= qb + 8; kt++) {
        const int kbase = c * WIN_ - WIN_ + kt * 64;
        if (kbase >= SS || kbase < 0) continue;

        {
            int r0 = tid >> 4;
            int dc = (tid & 15) * 4;
            #pragma unroll
            for (int p = 0; p < 8; p++) {
                int r = r0 + p * 8;
                *reinterpret_cast<uint4*>(&Ks[r * AST + dc]) =
                    *reinterpret_cast<const uint4*>(&Kg[(size_t)(kbase + r) * DD + dc]);
                *reinterpret_cast<uint4*>(&Vs[r * AST + dc]) =
                    *reinterpret_cast<const uint4*>(&Vg[(size_t)(kbase + r) * DD + dc]);
            }
        }
        __syncthreads();

        float s[8][4];
        #pragma unroll
        for (int nf = 0; nf < 8; nf++)
            #pragma unroll
            for (int r = 0; r < 4; r++) s[nf][r] = 0.f;

        #pragma unroll
        for (int ks = 0; ks < 8; ks++) {
            #pragma unroll
            for (int nf = 0; nf < 8; nf++) {
                uint32_t b[2];
                int base = (nf * 8 + grp) * AST + ks * 8 + qid;
                b[0] = Ks[base];
                b[1] = Ks[base + 4];
                mma_tf32(s[nf], qf[ks], b);
            }
        }

        float nm0 = m0, nm1 = m1;
        #pragma unroll
        for (int nf = 0; nf < 8; nf++) {
            int kp = kbase + nf * 8 + qid * 2;
            s[nf][0] = (kp     >= qp0 - WIN_ && kp     <= qp0 + WIN_) ? s[nf][0] : -1e30f;
            s[nf][1] = (kp + 1 >= qp0 - WIN_ && kp + 1 <= qp0 + WIN_) ? s[nf][1] : -1e30f;
            s[nf][2] = (kp     >= qp1 - WIN_ && kp     <= qp1 + WIN_) ? s[nf][2] : -1e30f;
            s[nf][3] = (kp + 1 >= qp1 - WIN_ && kp + 1 <= qp1 + WIN_) ? s[nf][3] : -1e30f;
            nm0 = fmaxf(nm0, fmaxf(s[nf][0], s[nf][1]));
            nm1 = fmaxf(nm1, fmaxf(s[nf][2], s[nf][3]));
        }
        nm0 = fmaxf(nm0, __shfl_xor_sync(0xffffffffu, nm0, 1));
        nm0 = fmaxf(nm0, __shfl_xor_sync(0xffffffffu, nm0, 2));
        nm1 = fmaxf(nm1, __shfl_xor_sync(0xffffffffu, nm1, 1));
        nm1 = fmaxf(nm1, __shfl_xor_sync(0xffffffffu, nm1, 2));

        float fac0 = __expf(m0 - nm0);
        float fac1 = __expf(m1 - nm1);
        m0 = nm0; m1 = nm1;

        float rs0 = 0.f, rs1 = 0.f;
        const int prow0 = (w * 16 + grp) * AST + qid * 2;
        const int prow1 = (w * 16 + grp + 8) * AST + qid * 2;
        #pragma unroll
        for (int nf = 0; nf < 8; nf++) {
            uint32_t u00 = f2tf(__expf(s[nf][0] - m0));
            uint32_t u01 = f2tf(__expf(s[nf][1] - m0));
            uint32_t u10 = f2tf(__expf(s[nf][2] - m1));
            uint32_t u11 = f2tf(__expf(s[nf][3] - m1));
            rs0 += __uint_as_float(u00) + __uint_as_float(u01);
            rs1 += __uint_as_float(u10) + __uint_as_float(u11);
            *reinterpret_cast<uint2*>(&Ps[prow0 + nf * 8]) = make_uint2(u00, u01);
            *reinterpret_cast<uint2*>(&Ps[prow1 + nf * 8]) = make_uint2(u10, u11);
        }
        rs0 += __shfl_xor_sync(0xffffffffu, rs0, 1);
        rs0 += __shfl_xor_sync(0xffffffffu, rs0, 2);
        rs1 += __shfl_xor_sync(0xffffffffu, rs1, 1);
        rs1 += __shfl_xor_sync(0xffffffffu, rs1, 2);
        l0 = l0 * fac0 + rs0;
        l1 = l1 * fac1 + rs1;

        #pragma unroll
        for (int nf = 0; nf < 8; nf++) {
            o[nf][0] *= fac0; o[nf][1] *= fac0;
            o[nf][2] *= fac1; o[nf][3] *= fac1;
        }

        #pragma unroll
        for (int ks = 0; ks < 8; ks++) {
            uint32_t a[4];
            int abase = (w * 16 + grp) * AST + ks * 8 + qid;
            a[0] = __float_as_uint(Ps[abase]);
            a[1] = __float_as_uint(Ps[abase + 8 * AST]);
            a[2] = __float_as_uint(Ps[abase + 4]);
            a[3] = __float_as_uint(Ps[abase + 8 * AST + 4]);
            #pragma unroll
            for (int nf = 0; nf < 8; nf++) {
                uint32_t b[2];
                int vbase = (ks * 8 + qid) * AST + nf * 8 + grp;
                b[0] = Vs[vbase];
                b[1] = Vs[vbase + 4 * AST];
                mma_tf32(o[nf], a, b);
            }
        }
        __syncthreads();
    }

    // epilogue: normalize + write ctx as tf32 bits
    const int b = bh >> 4, h = bh & 15;
    float inv0 = 1.f / l0, inv1 = 1.f / l1;
    const int row0 = q0 + w * 16 + grp;
    #pragma unroll
    for (int nf = 0; nf < 8; nf++) {
        int col = h * DD + nf * 8 + qid * 2;
        *reinterpret_cast<uint2*>(&g_ctx[((size_t)(b * SS + row0)) * EE + col]) =
            make_uint2(f2tf(o[nf][0] * inv0), f2tf(o[nf][1] * inv0));
        *reinterpret_cast<uint2*>(&g_ctx[((size_t)(b * SS + row0 + 8)) * EE + col]) =
            make_uint2(f2tf(o[nf][2] * inv1), f2tf(o[nf][3] * inv1));
    }
}

extern "C" void kernel_launch(void* const* d_in, const int* in_sizes, int n_in,
                              void* d_out, int out_size)
{
    (void)in_sizes; (void)n_in; (void)out_size;
    const float* x  = (const float*)d_in[0];
    const float* Wq = (const float*)d_in[1];
    const float* bq = (const float*)d_in[2];
    const float* Wk = (const float*)d_in[3];
    const float* bk = (const float*)d_in[4];
    const float* Wv = (const float*)d_in[5];
    const float* bv = (const float*)d_in[6];
    const float* Wo = (const float*)d_in[7];
    const float* bo = (const float*)d_in[8];
    float* out = (float*)d_out;

    cudaFuncSetAttribute(proj_mma<0>, cudaFuncAttributeMaxDynamicSharedMemorySize, SMEM_PROJ);
    cudaFuncSetAttribute(proj_mma<1>, cudaFuncAttributeMaxDynamicSharedMemorySize, SMEM_PROJ);
    cudaFuncSetAttribute(attn_mma_kernel, cudaFuncAttributeMaxDynamicSharedMemorySize, SMEM_ATTN);

    {
        size_t total4 = (XT_ELEMS + 4 * WT_ELEMS) / 4;
        int blocks = (int)((total4 + 255) / 256);
        conv_kernel<<<blocks, 256>>>(x, Wq, Wk, Wv, Wo);
    }

    dim3 gq(EE / 128, MM / 256, 3);
    proj_mma<0><<<gq, 512, SMEM_PROJ>>>(bq, bk, bv, nullptr);

    attn_mma_kernel<<<dim3(4, 16, BB * HH), 128, SMEM_ATTN>>>();

    dim3 go(EE / 128, MM / 256, 1);
    proj_mma<1><<<go, 512, SMEM_PROJ>>>(bo, nullptr, nullptr, out);
}

// round 9
// speedup vs baseline: 5.0143x; 1.0463x over previous
#include <cuda_runtime.h>
#include <math.h>
#include <stdint.h>

#define BB 2
#define SS 4096
#define EE 1024
#define HH 16
#define DD 64
#define WIN_ 256
#define MM (BB*SS)   // 8192

#define XT_ELEMS ((size_t)MM*EE)     // 8388608
#define WT_ELEMS ((size_t)EE*EE)     // 1048576

// scratch (allocation-free: __device__ globals)
// tf32 bit patterns everywhere the tensor cores read
static __device__ uint32_t g_xt[XT_ELEMS];             // x, tf32
static __device__ uint32_t g_wt[4*WT_ELEMS];           // Wq,Wk,Wv,Wo, tf32
static __device__ uint32_t g_q[(size_t)BB*HH*SS*DD];   // [b][h][s][d], rope'd + scaled, tf32
static __device__ uint32_t g_k[(size_t)BB*HH*SS*DD];   // [b][h][s][d], rope'd, tf32
static __device__ uint32_t g_v[(size_t)BB*HH*SS*DD];   // [b][h][s][d], tf32
static __device__ uint32_t g_ctx[(size_t)MM*EE];       // [b][s][e], tf32

// rope over the HEAD axis: angle = head_idx * 10000^{-(j%32)/32}, interleaved rotation
__device__ __forceinline__ void rope_pair(float& v0, float& v1, int h, int j) {
    const float C = 0.28782313662425572f; // ln(10000)/32
    float invA = __expf(-(float)( j      & 31) * C);
    float invB = __expf(-(float)((j + 1) & 31) * C);
    float sa, ca, sb, cb;
    __sincosf((float)h * invA, &sa, &ca);
    __sincosf((float)h * invB, &sb, &cb);
    float r0 = v0 * ca - v1 * sa;
    float r1 = v1 * cb + v0 * sb;
    v0 = r0; v1 = r1;
}

__device__ __forceinline__ uint32_t f2tf(float f) {
    uint32_t u;
    asm("cvt.rna.tf32.f32 %0, %1;" : "=r"(u) : "f"(f));
    return u;
}

__device__ __forceinline__ void mma_tf32(float (&c)[4], const uint32_t (&a)[4], const uint32_t (&b)[2]) {
    asm volatile(
        "mma.sync.aligned.m16n8k8.row.col.f32.tf32.tf32.f32 "
        "{%0,%1,%2,%3},{%4,%5,%6,%7},{%8,%9},{%0,%1,%2,%3};"
        : "+f"(c[0]), "+f"(c[1]), "+f"(c[2]), "+f"(c[3])
        : "r"(a[0]), "r"(a[1]), "r"(a[2]), "r"(a[3]), "r"(b[0]), "r"(b[1]));
}

// ldmatrix on 32-bit data: an 8x8-uint32 tile viewed as 8x16 b16 gives lane l
// word (l%4) of row (l/4) — exactly the tf32 mma fragment mapping.
__device__ __forceinline__ void ldsm_x4(uint32_t (&d)[4], uint32_t addr) {
    asm volatile("ldmatrix.sync.aligned.m8n8.x4.shared.b16 {%0,%1,%2,%3}, [%4];"
        : "=r"(d[0]), "=r"(d[1]), "=r"(d[2]), "=r"(d[3]) : "r"(addr));
}
__device__ __forceinline__ void ldsm_x2(uint32_t (&d)[2], uint32_t addr) {
    asm volatile("ldmatrix.sync.aligned.m8n8.x2.shared.b16 {%0,%1}, [%2];"
        : "=r"(d[0]), "=r"(d[1]) : "r"(addr));
}

__device__ __forceinline__ void cp16(uint32_t smem_addr, const void* gptr) {
    asm volatile("cp.async.cg.shared.global [%0], [%1], 16;" :: "r"(smem_addr), "l"(gptr));
}
#define CP_COMMIT() asm volatile("cp.async.commit_group;")
#define CP_WAIT1()  asm volatile("cp.async.wait_group 1;")

// ---------------- one-time tf32 conversion of x and W matrices ----------------
__global__ __launch_bounds__(256)
void conv_kernel(const float* __restrict__ x,
                 const float* __restrict__ wq, const float* __restrict__ wk,
                 const float* __restrict__ wv, const float* __restrict__ wo)
{
    size_t i4 = (size_t)blockIdx.x * 256 + threadIdx.x;
    const size_t x4 = XT_ELEMS / 4;
    const size_t w4 = WT_ELEMS / 4;
    if (i4 >= x4 + 4 * w4) return;
    const float* src; uint32_t* dst; size_t off;
    if (i4 < x4) { src = x; dst = g_xt; off = i4 * 4; }
    else {
        size_t j = i4 - x4;
        int w = (int)(j / w4);
        off = (j - (size_t)w * w4) * 4;
        src = (w == 0) ? wq : (w == 1) ? wk : (w == 2) ? wv : wo;
        dst = g_wt + (size_t)w * WT_ELEMS;
    }
    float4 v = *reinterpret_cast<const float4*>(src + off);
    *reinterpret_cast<uint4*>(dst + off) =
        make_uint4(f2tf(v.x), f2tf(v.y), f2tf(v.z), f2tf(v.w));
}

// ---------------- projection GEMM (TF32, cp.async 3-stage, 256x128 tile, ldmatrix) ----------------
// MODE 0: A = g_xt, W = g_wt[z]; rope epilogue; writes g_q/g_k/g_v [b,h,s,d] tf32
// MODE 1: A = g_ctx, W = g_wt[3]; writes d_out [m,n] fp32
#define ASTRIDE 36
#define STAGE_ELEMS ((256 + 128) * ASTRIDE)          // 13824 uint32
#define STAGE_BYTES (STAGE_ELEMS * 4)                // 55296
#define SMEM_PROJ   (3 * STAGE_BYTES)                // 165888

template<int MODE>
__global__ __launch_bounds__(512, 1)
void proj_mma(const float* __restrict__ b0, const float* __restrict__ b1,
              const float* __restrict__ b2, float* __restrict__ out)
{
    extern __shared__ uint32_t sm_u[];
    const uint32_t smem_b = (uint32_t)__cvta_generic_to_shared(sm_u);

    const int z = blockIdx.z;
    const uint32_t* A = (MODE == 1) ? g_ctx : g_xt;
    const uint32_t* W = g_wt + (size_t)((MODE == 1) ? 3 : z) * WT_ELEMS;
    const float* bias = (MODE == 1) ? b0 : (z == 0 ? b0 : (z == 1 ? b1 : b2));

    const int tid   = threadIdx.x;
    const int lane  = tid & 31;
    const int warp  = tid >> 5;            // 0..15
    const int warpM = warp >> 2;           // 0..3 -> 64-row slab
    const int warpN = warp & 3;            // 0..3 -> 32-col slab
    const int grp   = lane >> 2;           // 0..7
    const int qid   = lane & 3;            // 0..3
    const int mBase = blockIdx.y * 256;
    const int nBase = blockIdx.x * 128;

    const int ldRow = tid >> 3;            // 0..63
    const int ldCol = (tid & 7) * 4;       // 0..28

    // per-lane ldmatrix base offsets (bytes)
    const int sub = lane >> 3;             // 0..3
    const int rin = lane & 7;              // 0..7
    const uint32_t aFragOff = (uint32_t)((warpM * 64 + (sub & 1) * 8 + rin) * ASTRIDE + (sub >> 1) * 4) * 4;
    const uint32_t bFragOff = (uint32_t)((256 * ASTRIDE) + (warpN * 32 + rin) * ASTRIDE + (sub & 1) * 4) * 4;

    // async stage loader
    auto issue = [&](int stage, int k0) {
        uint32_t base = smem_b + stage * STAGE_BYTES;
        int kofs = k0 * 32 + ldCol;
        #pragma unroll
        for (int p = 0; p < 4; p++) {
            int r = ldRow + p * 64;
            cp16(base + (uint32_t)(r * ASTRIDE + ldCol) * 4,
                 A + (size_t)(mBase + r) * EE + kofs);
        }
        #pragma unroll
        for (int p = 0; p < 2; p++) {
            int r = ldRow + p * 64;
            cp16(base + (uint32_t)((256 * ASTRIDE) + r * ASTRIDE + ldCol) * 4,
                 W + (size_t)(nBase + r) * EE + kofs);
        }
    };

    float acc[4][4][4];
    #pragma unroll
    for (int mf = 0; mf < 4; mf++)
        #pragma unroll
        for (int nf = 0; nf < 4; nf++)
            #pragma unroll
            for (int r = 0; r < 4; r++) acc[mf][nf][r] = 0.f;

    const int NIT = EE / 32;   // 32
    issue(0, 0); CP_COMMIT();
    issue(1, 1); CP_COMMIT();

    int stage = 0;
    for (int k0 = 0; k0 < NIT; k0++) {
        CP_WAIT1();
        __syncthreads();
        if (k0 + 2 < NIT) {
            int ns = stage + 2; if (ns >= 3) ns -= 3;
            issue(ns, k0 + 2);
        }
        CP_COMMIT();

        const uint32_t aBase = smem_b + stage * STAGE_BYTES + aFragOff;
        const uint32_t bBase = smem_b + stage * STAGE_BYTES + bFragOff;

        #pragma unroll
        for (int ks = 0; ks < 4; ks++) {
            uint32_t af[4][4];
            #pragma unroll
            for (int mf = 0; mf < 4; mf++)
                ldsm_x4(af[mf], aBase + (uint32_t)(mf * 16 * ASTRIDE + ks * 8) * 4);
            uint32_t bf[4][2];
            #pragma unroll
            for (int nf = 0; nf < 4; nf++)
                ldsm_x2(bf[nf], bBase + (uint32_t)(nf * 8 * ASTRIDE + ks * 8) * 4);
            #pragma unroll
            for (int mf = 0; mf < 4; mf++)
                #pragma unroll
                for (int nf = 0; nf < 4; nf++)
                    mma_tf32(acc[mf][nf], af[mf], bf[nf]);
        }

        stage++; if (stage >= 3) stage = 0;
    }

    // epilogue: bias (+rope/scale for MODE 0), scatter
    #pragma unroll
    for (int mf = 0; mf < 4; mf++) {
        #pragma unroll
        for (int half = 0; half < 2; half++) {
            int row = mBase + warpM * 64 + mf * 16 + grp + half * 8;
            int bb   = row >> 12;
            int srow = row & 4095;
            #pragma unroll
            for (int nf = 0; nf < 4; nf++) {
                int col = nBase + warpN * 32 + nf * 8 + qid * 2;
                float v0 = acc[mf][nf][half * 2 + 0] + bias[col];
                float v1 = acc[mf][nf][half * 2 + 1] + bias[col + 1];
                if (MODE == 1) {
                    *reinterpret_cast<float2*>(&out[(size_t)row * EE + col]) = make_float2(v0, v1);
                } else {
                    int h = col >> 6;
                    int j = col & 63;     // even
                    if (z <= 1) rope_pair(v0, v1, h, j);
                    if (z == 0) { v0 *= 0.125f; v1 *= 0.125f; }
                    uint32_t* dst = (z == 0) ? g_q : (z == 1) ? g_k : g_v;
                    size_t idx = (((size_t)bb * HH + h) * SS + srow) * DD + j;
                    *reinterpret_cast<uint2*>(&dst[idx]) = make_uint2(f2tf(v0), f2tf(v1));
                }
            }
        }
    }
}

// ---------------- sliding-window attention (flash-style, TF32 tensor cores, ldmatrix) ----------------
// grid (qb=4, c=16, bh=32); block 128 (4 warps); each warp owns 16 query rows.
#define AST 68                                   // smem stride (uint32)
#define SMEM_ATTN (3 * 64 * AST * 4)             // Qs(->Ps) + Ks + Vs = 52224 B

__global__ __launch_bounds__(128)
void attn_mma_kernel()
{
    extern __shared__ uint32_t sm[];
    uint32_t* Qs = sm;                  // 64 x AST (reused as Ps after Q frags are in regs)
    uint32_t* Ks = sm + 64 * AST;
    uint32_t* Vs = sm + 2 * 64 * AST;
    float*    Ps = reinterpret_cast<float*>(Qs);
    const uint32_t smA = (uint32_t)__cvta_generic_to_shared(sm);

    const int qb = blockIdx.x;
    const int c  = blockIdx.y;
    const int bh = blockIdx.z;
    const int tid  = threadIdx.x;
    const int w    = tid >> 5;
    const int lane = tid & 31;
    const int grp  = lane >> 2;          // 0..7
    const int qid  = lane & 3;           // 0..3
    const int sub  = lane >> 3;          // 0..3
    const int rin  = lane & 7;           // 0..7

    const uint32_t* Qg = g_q + (size_t)bh * SS * DD;
    const uint32_t* Kg = g_k + (size_t)bh * SS * DD;
    const uint32_t* Vg = g_v + (size_t)bh * SS * DD;

    const int q0 = c * WIN_ + qb * 64;

    // ldmatrix fragment base offsets (bytes)
    const uint32_t qpFragOff = (uint32_t)((w * 16 + (sub & 1) * 8 + rin) * AST + (sub >> 1) * 4) * 4;  // A-frag (Q / P)
    const uint32_t kFragOff  = (uint32_t)(64 * AST + rin * AST + (sub & 1) * 4) * 4;                   // B-frag (K)

    {
        int r0 = tid >> 4;
        int dc = (tid & 15) * 4;
        #pragma unroll
        for (int p = 0; p < 8; p++) {
            int r = r0 + p * 8;
            *reinterpret_cast<uint4*>(&Qs[r * AST + dc]) =
                *reinterpret_cast<const uint4*>(&Qg[(size_t)(q0 + r) * DD + dc]);
        }
    }
    __syncthreads();

    uint32_t qf[8][4];
    #pragma unroll
    for (int ks = 0; ks < 8; ks++)
        ldsm_x4(qf[ks], smA + qpFragOff + (uint32_t)(ks * 8) * 4);

    float o[8][4];
    #pragma unroll
    for (int nf = 0; nf < 8; nf++)
        #pragma unroll
        for (int r = 0; r < 4; r++) o[nf][r] = 0.f;
    float m0 = -1e30f, m1 = -1e30f, l0 = 0.f, l1 = 0.f;

    const int qp0 = q0 + w * 16 + grp;
    const int qp1 = qp0 + 8;

    for (int kt = qb; kt <= qb + 8; kt++) {
        const int kbase = c * WIN_ - WIN_ + kt * 64;
        if (kbase >= SS || kbase < 0) continue;

        {
            int r0 = tid >> 4;
            int dc = (tid & 15) * 4;
            #pragma unroll
            for (int p = 0; p < 8; p++) {
                int r = r0 + p * 8;
                *reinterpret_cast<uint4*>(&Ks[r * AST + dc]) =
                    *reinterpret_cast<const uint4*>(&Kg[(size_t)(kbase + r) * DD + dc]);
                *reinterpret_cast<uint4*>(&Vs[r * AST + dc]) =
                    *reinterpret_cast<const uint4*>(&Vg[(size_t)(kbase + r) * DD + dc]);
            }
        }
        __syncthreads();

        float s[8][4];
        #pragma unroll
        for (int nf = 0; nf < 8; nf++)
            #pragma unroll
            for (int r = 0; r < 4; r++) s[nf][r] = 0.f;

        #pragma unroll
        for (int ks = 0; ks < 8; ks++) {
            #pragma unroll
            for (int nf = 0; nf < 8; nf++) {
                uint32_t b[2];
                ldsm_x2(b, smA + kFragOff + (uint32_t)(nf * 8 * AST + ks * 8) * 4);
                mma_tf32(s[nf], qf[ks], b);
            }
        }

        float nm0 = m0, nm1 = m1;
        #pragma unroll
        for (int nf = 0; nf < 8; nf++) {
            int kp = kbase + nf * 8 + qid * 2;
            s[nf][0] = (kp     >= qp0 - WIN_ && kp     <= qp0 + WIN_) ? s[nf][0] : -1e30f;
            s[nf][1] = (kp + 1 >= qp0 - WIN_ && kp + 1 <= qp0 + WIN_) ? s[nf][1] : -1e30f;
            s[nf][2] = (kp     >= qp1 - WIN_ && kp     <= qp1 + WIN_) ? s[nf][2] : -1e30f;
            s[nf][3] = (kp + 1 >= qp1 - WIN_ && kp + 1 <= qp1 + WIN_) ? s[nf][3] : -1e30f;
            nm0 = fmaxf(nm0, fmaxf(s[nf][0], s[nf][1]));
            nm1 = fmaxf(nm1, fmaxf(s[nf][2], s[nf][3]));
        }
        nm0 = fmaxf(nm0, __shfl_xor_sync(0xffffffffu, nm0, 1));
        nm0 = fmaxf(nm0, __shfl_xor_sync(0xffffffffu, nm0, 2));
        nm1 = fmaxf(nm1, __shfl_xor_sync(0xffffffffu, nm1, 1));
        nm1 = fmaxf(nm1, __shfl_xor_sync(0xffffffffu, nm1, 2));

        float fac0 = __expf(m0 - nm0);
        float fac1 = __expf(m1 - nm1);
        m0 = nm0; m1 = nm1;

        float rs0 = 0.f, rs1 = 0.f;
        const int prow0 = (w * 16 + grp) * AST + qid * 2;
        const int prow1 = (w * 16 + grp + 8) * AST + qid * 2;
        #pragma unroll
        for (int nf = 0; nf < 8; nf++) {
            uint32_t u00 = f2tf(__expf(s[nf][0] - m0));
            uint32_t u01 = f2tf(__expf(s[nf][1] - m0));
            uint32_t u10 = f2tf(__expf(s[nf][2] - m1));
            uint32_t u11 = f2tf(__expf(s[nf][3] - m1));
            rs0 += __uint_as_float(u00) + __uint_as_float(u01);
            rs1 += __uint_as_float(u10) + __uint_as_float(u11);
            *reinterpret_cast<uint2*>(&Ps[prow0 + nf * 8]) = make_uint2(u00, u01);
            *reinterpret_cast<uint2*>(&Ps[prow1 + nf * 8]) = make_uint2(u10, u11);
        }
        rs0 += __shfl_xor_sync(0xffffffffu, rs0, 1);
        rs0 += __shfl_xor_sync(0xffffffffu, rs0, 2);
        rs1 += __shfl_xor_sync(0xffffffffu, rs1, 1);
        rs1 += __shfl_xor_sync(0xffffffffu, rs1, 2);
        l0 = l0 * fac0 + rs0;
        l1 = l1 * fac1 + rs1;

        #pragma unroll
        for (int nf = 0; nf < 8; nf++) {
            o[nf][0] *= fac0; o[nf][1] *= fac0;
            o[nf][2] *= fac1; o[nf][3] *= fac1;
        }
        __syncwarp();   // Ps rows warp-private; order stores before cross-lane ldmatrix reads

        #pragma unroll
        for (int ks = 0; ks < 8; ks++) {
            uint32_t a[4];
            ldsm_x4(a, smA + qpFragOff + (uint32_t)(ks * 8) * 4);
            #pragma unroll
            for (int nf = 0; nf < 8; nf++) {
                uint32_t b[2];
                int vbase = (ks * 8 + qid) * AST + nf * 8 + grp;
                b[0] = Vs[vbase];
                b[1] = Vs[vbase + 4 * AST];
                mma_tf32(o[nf], a, b);
            }
        }
        __syncthreads();
    }

    // epilogue: normalize + write ctx as tf32 bits
    const int b = bh >> 4, h = bh & 15;
    float inv0 = 1.f / l0, inv1 = 1.f / l1;
    const int row0 = q0 + w * 16 + grp;
    #pragma unroll
    for (int nf = 0; nf < 8; nf++) {
        int col = h * DD + nf * 8 + qid * 2;
        *reinterpret_cast<uint2*>(&g_ctx[((size_t)(b * SS + row0)) * EE + col]) =
            make_uint2(f2tf(o[nf][0] * inv0), f2tf(o[nf][1] * inv0));
        *reinterpret_cast<uint2*>(&g_ctx[((size_t)(b * SS + row0 + 8)) * EE + col]) =
            make_uint2(f2tf(o[nf][2] * inv1), f2tf(o[nf][3] * inv1));
    }
}

extern "C" void kernel_launch(void* const* d_in, const int* in_sizes, int n_in,
                              void* d_out, int out_size)
{
    (void)in_sizes; (void)n_in; (void)out_size;
    const float* x  = (const float*)d_in[0];
    const float* Wq = (const float*)d_in[1];
    const float* bq = (const float*)d_in[2];
    const float* Wk = (const float*)d_in[3];
    const float* bk = (const float*)d_in[4];
    const float* Wv = (const float*)d_in[5];
    const float* bv = (const float*)d_in[6];
    const float* Wo = (const float*)d_in[7];
    const float* bo = (const float*)d_in[8];
    float* out = (float*)d_out;

    cudaFuncSetAttribute(proj_mma<0>, cudaFuncAttributeMaxDynamicSharedMemorySize, SMEM_PROJ);
    cudaFuncSetAttribute(proj_mma<1>, cudaFuncAttributeMaxDynamicSharedMemorySize, SMEM_PROJ);
    cudaFuncSetAttribute(attn_mma_kernel, cudaFuncAttributeMaxDynamicSharedMemorySize, SMEM_ATTN);

    {
        size_t total4 = (XT_ELEMS + 4 * WT_ELEMS) / 4;
        int blocks = (int)((total4 + 255) / 256);
        conv_kernel<<<blocks, 256>>>(x, Wq, Wk, Wv, Wo);
    }

    dim3 gq(EE / 128, MM / 256, 3);
    proj_mma<0><<<gq, 512, SMEM_PROJ>>>(bq, bk, bv, nullptr);

    attn_mma_kernel<<<dim3(4, 16, BB * HH), 128, SMEM_ATTN>>>();

    dim3 go(EE / 128, MM / 256, 1);
    proj_mma<1><<<go, 512, SMEM_PROJ>>>(bo, nullptr, nullptr, out);
}